// round 6
// baseline (speedup 1.0000x reference)
#include <cuda_runtime.h>
#include <cuda_bf16.h>
#include <cstdint>
#include <math.h>

// Problem constants
#define Bb 4
#define Ts 2048
#define Cc 1024
#define Hh 16
#define Dd 64
#define Mtot (Bb*Ts)        // 8192
#define Nqkv (3*Cc)         // 3072
#define Kdim Cc             // 1024

// ---------------------------------------------------------------------------
// Scratch (__device__ globals; allocation-guard safe)
// ---------------------------------------------------------------------------
__device__ __align__(128) float g_q[Bb*Hh*Ts*Dd];
__device__ __align__(128) float g_k[Bb*Hh*Ts*Dd];
__device__ __align__(128) float g_v[Bb*Hh*Ts*Dd];
__device__ __align__(128) float g_y[Bb*Ts*Cc];
__device__ __align__(128) float g_shadow[Mtot*Nqkv];   // MMA diagnostic sink

// ---------------------------------------------------------------------------
// PROVEN SIMT pipeline (round 1, verbatim): qkv GEMM, attn, proj GEMM
// ---------------------------------------------------------------------------
__global__ __launch_bounds__(256)
void qkv_gemm_kernel(const float* __restrict__ X,
                     const float* __restrict__ W,
                     const float* __restrict__ bias)
{
    const int K = Cc, N = 3 * Cc;
    __shared__ __align__(16) float As[16][132];
    __shared__ __align__(16) float Bs[16][128];

    const int tid = threadIdx.x;
    const int ty = tid >> 4, tx = tid & 15;
    const int m0 = blockIdx.y * 128;
    const int n0 = blockIdx.x * 128;

    float acc[8][8];
    #pragma unroll
    for (int i = 0; i < 8; i++)
        #pragma unroll
        for (int j = 0; j < 8; j++) acc[i][j] = 0.f;

    const int arow = tid >> 2;
    const int acol = (tid & 3) << 2;
    const int brw  = tid >> 5;
    const int bcl  = (tid & 31) << 2;

    for (int k0 = 0; k0 < K; k0 += 16) {
        #pragma unroll
        for (int it = 0; it < 2; it++) {
            int r = arow + it * 64;
            float4 va = *(const float4*)(X + (size_t)(m0 + r) * K + k0 + acol);
            As[acol+0][r] = va.x;
            As[acol+1][r] = va.y;
            As[acol+2][r] = va.z;
            As[acol+3][r] = va.w;
        }
        #pragma unroll
        for (int it = 0; it < 2; it++) {
            int r = brw + it * 8;
            *(float4*)(&Bs[r][bcl]) =
                *(const float4*)(W + (size_t)(k0 + r) * N + n0 + bcl);
        }
        __syncthreads();
        #pragma unroll
        for (int kk = 0; kk < 16; kk++) {
            float ra[8], rb[8];
            *(float4*)(ra)     = *(const float4*)(&As[kk][ty*8]);
            *(float4*)(ra + 4) = *(const float4*)(&As[kk][ty*8 + 4]);
            *(float4*)(rb)     = *(const float4*)(&Bs[kk][tx*8]);
            *(float4*)(rb + 4) = *(const float4*)(&Bs[kk][tx*8 + 4]);
            #pragma unroll
            for (int i = 0; i < 8; i++)
                #pragma unroll
                for (int j = 0; j < 8; j++)
                    acc[i][j] = fmaf(ra[i], rb[j], acc[i][j]);
        }
        __syncthreads();
    }

    #pragma unroll
    for (int i = 0; i < 8; i++) {
        int m = m0 + ty*8 + i;
        int b = m >> 11;
        int t = m & (Ts - 1);
        #pragma unroll
        for (int j = 0; j < 8; j++) {
            int n = n0 + tx*8 + j;
            float val = acc[i][j] + bias[n];
            int which = n >> 10;
            int c = n & (Cc - 1);
            int h = c >> 6, d = c & 63;
            float* dst = (which == 0) ? g_q : (which == 1 ? g_k : g_v);
            dst[(((size_t)(b * Hh + h) << 11) + t) * Dd + d] = val;
        }
    }
}

__global__ __launch_bounds__(256)
void attn_kernel()
{
    extern __shared__ float sm[];
    float* Qs = sm;
    float* Ks = sm + 64*68;
    float* Vs = sm + 2*64*68;
    float* Ps = sm + 3*64*68;

    const int tid = threadIdx.x;
    const int ty = tid >> 4, tx = tid & 15;
    const int qt = blockIdx.x;
    const int bh = blockIdx.y;

    const float* Qg = g_q + (size_t)bh * Ts * Dd;
    const float* Kg = g_k + (size_t)bh * Ts * Dd;
    const float* Vg = g_v + (size_t)bh * Ts * Dd;

    #pragma unroll
    for (int it = 0; it < 4; it++) {
        int idx = tid + it * 256;
        int r  = idx >> 4;
        int d4 = (idx & 15) << 2;
        float4 v = *(const float4*)(Qg + (size_t)(qt*64 + r) * Dd + d4);
        Qs[(d4+0)*68 + r] = v.x * 0.125f;
        Qs[(d4+1)*68 + r] = v.y * 0.125f;
        Qs[(d4+2)*68 + r] = v.z * 0.125f;
        Qs[(d4+3)*68 + r] = v.w * 0.125f;
    }

    float m_i[4], l_i[4], acc[4][4];
    #pragma unroll
    for (int i = 0; i < 4; i++) {
        m_i[i] = -1e30f;
        l_i[i] = 0.f;
        #pragma unroll
        for (int j = 0; j < 4; j++) acc[i][j] = 0.f;
    }

    for (int kt = 0; kt <= qt; kt++) {
        __syncthreads();
        #pragma unroll
        for (int it = 0; it < 4; it++) {
            int idx = tid + it * 256;
            int r  = idx >> 4;
            int d4 = (idx & 15) << 2;
            float4 kv = *(const float4*)(Kg + (size_t)(kt*64 + r) * Dd + d4);
            Ks[(d4+0)*68 + r] = kv.x;
            Ks[(d4+1)*68 + r] = kv.y;
            Ks[(d4+2)*68 + r] = kv.z;
            Ks[(d4+3)*68 + r] = kv.w;
            *(float4*)(&Vs[r*68 + d4]) =
                *(const float4*)(Vg + (size_t)(kt*64 + r) * Dd + d4);
        }
        __syncthreads();

        float s[4][4];
        #pragma unroll
        for (int i = 0; i < 4; i++)
            #pragma unroll
            for (int j = 0; j < 4; j++) s[i][j] = 0.f;

        #pragma unroll 4
        for (int d = 0; d < 64; d++) {
            float rq[4], rk[4];
            *(float4*)rq = *(const float4*)(Qs + d*68 + ty*4);
            *(float4*)rk = *(const float4*)(Ks + d*68 + tx*4);
            #pragma unroll
            for (int i = 0; i < 4; i++)
                #pragma unroll
                for (int j = 0; j < 4; j++)
                    s[i][j] = fmaf(rq[i], rk[j], s[i][j]);
        }

        if (kt == qt) {
            #pragma unroll
            for (int i = 0; i < 4; i++) {
                int r = ty*4 + i;
                #pragma unroll
                for (int j = 0; j < 4; j++) {
                    int cix = tx*4 + j;
                    if (cix > r) s[i][j] = -1e30f;
                }
            }
        }

        #pragma unroll
        for (int i = 0; i < 4; i++) {
            float mx = fmaxf(fmaxf(s[i][0], s[i][1]), fmaxf(s[i][2], s[i][3]));
            #pragma unroll
            for (int off = 8; off > 0; off >>= 1)
                mx = fmaxf(mx, __shfl_xor_sync(0xffffffffu, mx, off));
            float mnew = fmaxf(m_i[i], mx);
            float cf = __expf(m_i[i] - mnew);
            m_i[i] = mnew;
            float ps = 0.f;
            #pragma unroll
            for (int j = 0; j < 4; j++) {
                float p = __expf(s[i][j] - mnew);
                s[i][j] = p;
                ps += p;
            }
            #pragma unroll
            for (int off = 8; off > 0; off >>= 1)
                ps += __shfl_xor_sync(0xffffffffu, ps, off);
            l_i[i] = l_i[i] * cf + ps;
            #pragma unroll
            for (int j = 0; j < 4; j++) {
                acc[i][j] *= cf;
                Ps[(tx*4 + j)*68 + ty*4 + i] = s[i][j];
            }
        }
        __syncthreads();

        #pragma unroll 4
        for (int s0 = 0; s0 < 64; s0++) {
            float rp[4], rv[4];
            *(float4*)rp = *(const float4*)(Ps + s0*68 + ty*4);
            *(float4*)rv = *(const float4*)(Vs + s0*68 + tx*4);
            #pragma unroll
            for (int i = 0; i < 4; i++)
                #pragma unroll
                for (int j = 0; j < 4; j++)
                    acc[i][j] = fmaf(rp[i], rv[j], acc[i][j]);
        }
    }

    int b = bh >> 4, h = bh & 15;
    #pragma unroll
    for (int i = 0; i < 4; i++) {
        float inv = 1.0f / l_i[i];
        int t = qt*64 + ty*4 + i;
        #pragma unroll
        for (int j = 0; j < 4; j++) {
            int d = tx*4 + j;
            g_y[(size_t)(b * Ts + t) * Cc + h * Dd + d] = acc[i][j] * inv;
        }
    }
}

__global__ __launch_bounds__(256)
void proj_gemm_kernel(const float* __restrict__ W,
                      const float* __restrict__ bias,
                      float* __restrict__ out)
{
    const int K = Cc, N = Cc;
    __shared__ __align__(16) float As[16][132];
    __shared__ __align__(16) float Bs[16][128];

    const int tid = threadIdx.x;
    const int ty = tid >> 4, tx = tid & 15;
    const int m0 = blockIdx.y * 128;
    const int n0 = blockIdx.x * 128;

    float acc[8][8];
    #pragma unroll
    for (int i = 0; i < 8; i++)
        #pragma unroll
        for (int j = 0; j < 8; j++) acc[i][j] = 0.f;

    const int arow = tid >> 2;
    const int acol = (tid & 3) << 2;
    const int brw  = tid >> 5;
    const int bcl  = (tid & 31) << 2;

    for (int k0 = 0; k0 < K; k0 += 16) {
        #pragma unroll
        for (int it = 0; it < 2; it++) {
            int r = arow + it * 64;
            float4 va = *(const float4*)(g_y + (size_t)(m0 + r) * K + k0 + acol);
            As[acol+0][r] = va.x;
            As[acol+1][r] = va.y;
            As[acol+2][r] = va.z;
            As[acol+3][r] = va.w;
        }
        #pragma unroll
        for (int it = 0; it < 2; it++) {
            int r = brw + it * 8;
            *(float4*)(&Bs[r][bcl]) =
                *(const float4*)(W + (size_t)(k0 + r) * N + n0 + bcl);
        }
        __syncthreads();
        #pragma unroll
        for (int kk = 0; kk < 16; kk++) {
            float ra[8], rb[8];
            *(float4*)(ra)     = *(const float4*)(&As[kk][ty*8]);
            *(float4*)(ra + 4) = *(const float4*)(&As[kk][ty*8 + 4]);
            *(float4*)(rb)     = *(const float4*)(&Bs[kk][tx*8]);
            *(float4*)(rb + 4) = *(const float4*)(&Bs[kk][tx*8 + 4]);
            #pragma unroll
            for (int i = 0; i < 8; i++)
                #pragma unroll
                for (int j = 0; j < 8; j++)
                    acc[i][j] = fmaf(ra[i], rb[j], acc[i][j]);
        }
        __syncthreads();
    }

    #pragma unroll
    for (int i = 0; i < 8; i++) {
        int m = m0 + ty*8 + i;
        #pragma unroll
        for (int j = 0; j < 8; j++) {
            int n = n0 + tx*8 + j;
            out[(size_t)m * N + n] = acc[i][j] + bias[n];
        }
    }
}

// ---------------------------------------------------------------------------
// DIAGNOSTIC SHADOW: round-5 MMA compute core, writes only to g_shadow.
// K-loop repeated 4x so it is unambiguously the largest launch in ncu.
// ---------------------------------------------------------------------------
#define MMA_BF16(c, a, b) asm volatile( \
    "mma.sync.aligned.m16n8k16.row.col.f32.bf16.bf16.f32 " \
    "{%0,%1,%2,%3}, {%4,%5,%6,%7}, {%8,%9}, {%0,%1,%2,%3};" \
    : "+f"((c)[0]), "+f"((c)[1]), "+f"((c)[2]), "+f"((c)[3]) \
    : "r"((a)[0]), "r"((a)[1]), "r"((a)[2]), "r"((a)[3]), \
      "r"((b)[0]), "r"((b)[1]))

__device__ __forceinline__ void split2(float a, __nv_bfloat16& h, __nv_bfloat16& l) {
    __nv_bfloat16 hh = __float2bfloat16(a);
    l = __float2bfloat16(a - __bfloat162float(hh));
    h = hh;
}
__device__ __forceinline__ uint32_t pack2(__nv_bfloat16 a, __nv_bfloat16 b) {
    __nv_bfloat162 p = __halves2bfloat162(a, b);
    return *(uint32_t*)&p;
}

#define BM 128
#define BN 128
#define BK 32
#define KPAD 40

__global__ __launch_bounds__(256)
void shadow_mma_kernel(const float* __restrict__ A,
                       const float* __restrict__ W,
                       const float* __restrict__ bias, int N)
{
    __shared__ __align__(16) __nv_bfloat16 sA[2][BM * KPAD];
    __shared__ __align__(16) __nv_bfloat16 sB[2][BN * KPAD];

    const int tid = threadIdx.x;
    const int l = tid & 31;
    const int wid = tid >> 5;
    const int wm = wid & 3;
    const int wn = wid >> 2;
    const int m0 = blockIdx.y * BM;
    const int n0 = blockIdx.x * BN;
    const int qr = l >> 2;
    const int qc = l & 3;

    float acc[2][8][4];
    #pragma unroll
    for (int i = 0; i < 2; i++)
        #pragma unroll
        for (int j = 0; j < 8; j++)
            #pragma unroll
            for (int q = 0; q < 4; q++) acc[i][j][q] = 0.f;

    const int arw = tid >> 3;
    const int acl = (tid & 7) * 4;
    const int bkk = tid >> 5;
    const int bnn = (tid & 31) * 4;

    for (int rep = 0; rep < 4; rep++) {
        for (int kc = 0; kc < Kdim / BK; kc++) {
            const int k0 = kc * BK;
            __syncthreads();

            #pragma unroll
            for (int pass = 0; pass < 4; pass++) {
                const int r = arw + pass * 32;
                float4 av = *(const float4*)&A[(size_t)(m0 + r) * Kdim + k0 + acl];
                __nv_bfloat16 h0,l0,h1,l1,h2,l2,h3,l3;
                split2(av.x, h0, l0); split2(av.y, h1, l1);
                split2(av.z, h2, l2); split2(av.w, h3, l3);
                *(uint32_t*)&sA[0][r * KPAD + acl]     = pack2(h0, h1);
                *(uint32_t*)&sA[0][r * KPAD + acl + 2] = pack2(h2, h3);
                *(uint32_t*)&sA[1][r * KPAD + acl]     = pack2(l0, l1);
                *(uint32_t*)&sA[1][r * KPAD + acl + 2] = pack2(l2, l3);

                const int kk = bkk + pass * 8;
                float4 bv = *(const float4*)&W[(size_t)(k0 + kk) * N + n0 + bnn];
                __nv_bfloat16 bh, bl;
                split2(bv.x, bh, bl);
                sB[0][(bnn + 0) * KPAD + kk] = bh; sB[1][(bnn + 0) * KPAD + kk] = bl;
                split2(bv.y, bh, bl);
                sB[0][(bnn + 1) * KPAD + kk] = bh; sB[1][(bnn + 1) * KPAD + kk] = bl;
                split2(bv.z, bh, bl);
                sB[0][(bnn + 2) * KPAD + kk] = bh; sB[1][(bnn + 2) * KPAD + kk] = bl;
                split2(bv.w, bh, bl);
                sB[0][(bnn + 3) * KPAD + kk] = bh; sB[1][(bnn + 3) * KPAD + kk] = bl;
            }
            __syncthreads();

            #pragma unroll
            for (int kk = 0; kk < 2; kk++) {
                const int kb = kk * 16 + qc * 2;
                uint32_t bh[8][2], bl[8][2];
                #pragma unroll
                for (int nb = 0; nb < 8; nb++) {
                    const int nrow = wn * 64 + nb * 8 + qr;
                    bh[nb][0] = *(const uint32_t*)&sB[0][nrow * KPAD + kb];
                    bh[nb][1] = *(const uint32_t*)&sB[0][nrow * KPAD + kb + 8];
                    bl[nb][0] = *(const uint32_t*)&sB[1][nrow * KPAD + kb];
                    bl[nb][1] = *(const uint32_t*)&sB[1][nrow * KPAD + kb + 8];
                }
                #pragma unroll
                for (int mb = 0; mb < 2; mb++) {
                    const int arow = wm * 32 + mb * 16 + qr;
                    uint32_t ah[4], al[4];
                    ah[0] = *(const uint32_t*)&sA[0][arow * KPAD + kb];
                    ah[1] = *(const uint32_t*)&sA[0][(arow + 8) * KPAD + kb];
                    ah[2] = *(const uint32_t*)&sA[0][arow * KPAD + kb + 8];
                    ah[3] = *(const uint32_t*)&sA[0][(arow + 8) * KPAD + kb + 8];
                    al[0] = *(const uint32_t*)&sA[1][arow * KPAD + kb];
                    al[1] = *(const uint32_t*)&sA[1][(arow + 8) * KPAD + kb];
                    al[2] = *(const uint32_t*)&sA[1][arow * KPAD + kb + 8];
                    al[3] = *(const uint32_t*)&sA[1][(arow + 8) * KPAD + kb + 8];
                    #pragma unroll
                    for (int nb = 0; nb < 8; nb++) {
                        MMA_BF16(acc[mb][nb], ah, bh[nb]);
                        MMA_BF16(acc[mb][nb], ah, bl[nb]);
                        MMA_BF16(acc[mb][nb], al, bh[nb]);
                    }
                }
            }
        }
    }

    // Write to dedicated shadow sink (never read by the real pipeline)
    #pragma unroll
    for (int mb = 0; mb < 2; mb++) {
        #pragma unroll
        for (int nb = 0; nb < 8; nb++) {
            const int col = wn * 64 + nb * 8 + qc * 2;
            const int n = n0 + col;
            const float bv0 = bias[n];
            const float bv1 = bias[n + 1];
            #pragma unroll
            for (int half = 0; half < 2; half++) {
                const int m = m0 + wm * 32 + mb * 16 + qr + half * 8;
                g_shadow[(size_t)m * Nqkv + n]     = acc[mb][nb][half*2+0] + bv0;
                g_shadow[(size_t)m * Nqkv + n + 1] = acc[mb][nb][half*2+1] + bv1;
            }
        }
    }
}

// ---------------------------------------------------------------------------
extern "C" void kernel_launch(void* const* d_in, const int* in_sizes, int n_in,
                              void* d_out, int out_size)
{
    (void)in_sizes; (void)n_in; (void)out_size;
    const float* x     = (const float*)d_in[0];
    const float* w_qkv = (const float*)d_in[1];
    const float* b_qkv = (const float*)d_in[2];
    const float* w_out = (const float*)d_in[3];
    const float* b_out = (const float*)d_in[4];
    float* out = (float*)d_out;

    cudaFuncSetAttribute(attn_kernel,
                         cudaFuncAttributeMaxDynamicSharedMemorySize,
                         4 * 64 * 68 * (int)sizeof(float));

    // PROVEN pipeline -> d_out
    qkv_gemm_kernel<<<dim3(3*Cc/128, (Bb*Ts)/128), 256>>>(x, w_qkv, b_qkv);
    attn_kernel<<<dim3(Ts/64, Bb*Hh), 256, 4*64*68*(int)sizeof(float)>>>();
    proj_gemm_kernel<<<dim3(Cc/128, (Bb*Ts)/128), 256>>>(w_out, b_out, out);

    // DIAGNOSTIC: full-size MMA shadow (writes only g_shadow; 4x repeated)
    shadow_mma_kernel<<<dim3(Nqkv/BN, Mtot/BM), 256>>>(x, w_qkv, b_qkv, Nqkv);
}

// round 8
// speedup vs baseline: 2.8653x; 2.8653x over previous
#include <cuda_runtime.h>
#include <cuda_bf16.h>
#include <cstdint>
#include <math.h>

// Problem constants
#define Bb 4
#define Ts 2048
#define Cc 1024
#define Hh 16
#define Dd 64
#define Mtot (Bb*Ts)        // 8192
#define Nqkv (3*Cc)         // 3072
#define Kdim Cc             // 1024

// ---------------------------------------------------------------------------
// Scratch (__device__ globals). RULE (round-7 lesson): these symbols are ONLY
// referenced from device code — NEVER passed as kernel arguments from host.
// ---------------------------------------------------------------------------
__device__ __align__(128) float g_q[Bb*Hh*Ts*Dd];
__device__ __align__(128) float g_k[Bb*Hh*Ts*Dd];
__device__ __align__(128) float g_v[Bb*Hh*Ts*Dd];
__device__ __align__(128) float g_y[Bb*Ts*Cc];

// ---------------------------------------------------------------------------
// MMA core helpers (execution proven by round-6 shadow)
// ---------------------------------------------------------------------------
#define MMA_BF16(c, a, b) asm volatile( \
    "mma.sync.aligned.m16n8k16.row.col.f32.bf16.bf16.f32 " \
    "{%0,%1,%2,%3}, {%4,%5,%6,%7}, {%8,%9}, {%0,%1,%2,%3};" \
    : "+f"((c)[0]), "+f"((c)[1]), "+f"((c)[2]), "+f"((c)[3]) \
    : "r"((a)[0]), "r"((a)[1]), "r"((a)[2]), "r"((a)[3]), \
      "r"((b)[0]), "r"((b)[1]))

__device__ __forceinline__ void split2(float a, __nv_bfloat16& h, __nv_bfloat16& l) {
    __nv_bfloat16 hh = __float2bfloat16(a);
    l = __float2bfloat16(a - __bfloat162float(hh));
    h = hh;
}
__device__ __forceinline__ uint32_t pack2(__nv_bfloat16 a, __nv_bfloat16 b) {
    __nv_bfloat162 p = __halves2bfloat162(a, b);
    return *(uint32_t*)&p;
}

#define BM 128
#define BN 128
#define BK 32
#define KPAD 40

// ---------------------------------------------------------------------------
// 3xBF16 warp-MMA GEMM (compute core identical to round-6-proven shadow).
// MODE 0: A = Ap (harness ptr), N = 3072, epilogue scatters to g_q/g_k/g_v.
// MODE 1: A = g_y (device-side symbol ref), N = 1024, epilogue -> outp.
// ---------------------------------------------------------------------------
template<int MODE, int N>
__global__ __launch_bounds__(256)
void gemm_mma(const float* __restrict__ Ap,
              const float* __restrict__ W,
              const float* __restrict__ bias,
              float* __restrict__ outp)
{
    const float* __restrict__ A = (MODE == 0) ? Ap : (const float*)g_y;

    __shared__ __align__(16) __nv_bfloat16 sA[2][BM * KPAD];
    __shared__ __align__(16) __nv_bfloat16 sB[2][BN * KPAD];

    const int tid = threadIdx.x;
    const int l = tid & 31;
    const int wid = tid >> 5;
    const int wm = wid & 3;
    const int wn = wid >> 2;
    const int m0 = blockIdx.y * BM;
    const int n0 = blockIdx.x * BN;
    const int qr = l >> 2;
    const int qc = l & 3;

    float acc[2][8][4];
    #pragma unroll
    for (int i = 0; i < 2; i++)
        #pragma unroll
        for (int j = 0; j < 8; j++)
            #pragma unroll
            for (int q = 0; q < 4; q++) acc[i][j][q] = 0.f;

    const int arw = tid >> 3;
    const int acl = (tid & 7) * 4;
    const int bkk = tid >> 5;
    const int bnn = (tid & 31) * 4;

    for (int kc = 0; kc < Kdim / BK; kc++) {
        const int k0 = kc * BK;
        __syncthreads();

        #pragma unroll
        for (int pass = 0; pass < 4; pass++) {
            const int r = arw + pass * 32;
            float4 av = *(const float4*)&A[(size_t)(m0 + r) * Kdim + k0 + acl];
            __nv_bfloat16 h0,l0,h1,l1,h2,l2,h3,l3;
            split2(av.x, h0, l0); split2(av.y, h1, l1);
            split2(av.z, h2, l2); split2(av.w, h3, l3);
            *(uint32_t*)&sA[0][r * KPAD + acl]     = pack2(h0, h1);
            *(uint32_t*)&sA[0][r * KPAD + acl + 2] = pack2(h2, h3);
            *(uint32_t*)&sA[1][r * KPAD + acl]     = pack2(l0, l1);
            *(uint32_t*)&sA[1][r * KPAD + acl + 2] = pack2(l2, l3);

            const int kk = bkk + pass * 8;
            float4 bv = *(const float4*)&W[(size_t)(k0 + kk) * N + n0 + bnn];
            __nv_bfloat16 bh, bl;
            split2(bv.x, bh, bl);
            sB[0][(bnn + 0) * KPAD + kk] = bh; sB[1][(bnn + 0) * KPAD + kk] = bl;
            split2(bv.y, bh, bl);
            sB[0][(bnn + 1) * KPAD + kk] = bh; sB[1][(bnn + 1) * KPAD + kk] = bl;
            split2(bv.z, bh, bl);
            sB[0][(bnn + 2) * KPAD + kk] = bh; sB[1][(bnn + 2) * KPAD + kk] = bl;
            split2(bv.w, bh, bl);
            sB[0][(bnn + 3) * KPAD + kk] = bh; sB[1][(bnn + 3) * KPAD + kk] = bl;
        }
        __syncthreads();

        #pragma unroll
        for (int kk = 0; kk < 2; kk++) {
            const int kb = kk * 16 + qc * 2;
            uint32_t bh[8][2], bl[8][2];
            #pragma unroll
            for (int nb = 0; nb < 8; nb++) {
                const int nrow = wn * 64 + nb * 8 + qr;
                bh[nb][0] = *(const uint32_t*)&sB[0][nrow * KPAD + kb];
                bh[nb][1] = *(const uint32_t*)&sB[0][nrow * KPAD + kb + 8];
                bl[nb][0] = *(const uint32_t*)&sB[1][nrow * KPAD + kb];
                bl[nb][1] = *(const uint32_t*)&sB[1][nrow * KPAD + kb + 8];
            }
            #pragma unroll
            for (int mb = 0; mb < 2; mb++) {
                const int arow = wm * 32 + mb * 16 + qr;
                uint32_t ah[4], al[4];
                ah[0] = *(const uint32_t*)&sA[0][arow * KPAD + kb];
                ah[1] = *(const uint32_t*)&sA[0][(arow + 8) * KPAD + kb];
                ah[2] = *(const uint32_t*)&sA[0][arow * KPAD + kb + 8];
                ah[3] = *(const uint32_t*)&sA[0][(arow + 8) * KPAD + kb + 8];
                al[0] = *(const uint32_t*)&sA[1][arow * KPAD + kb];
                al[1] = *(const uint32_t*)&sA[1][(arow + 8) * KPAD + kb];
                al[2] = *(const uint32_t*)&sA[1][arow * KPAD + kb + 8];
                al[3] = *(const uint32_t*)&sA[1][(arow + 8) * KPAD + kb + 8];
                #pragma unroll
                for (int nb = 0; nb < 8; nb++) {
                    MMA_BF16(acc[mb][nb], ah, bh[nb]);
                    MMA_BF16(acc[mb][nb], ah, bl[nb]);
                    MMA_BF16(acc[mb][nb], al, bh[nb]);
                }
            }
        }
    }

    // ---- epilogue ----
    #pragma unroll
    for (int mb = 0; mb < 2; mb++) {
        #pragma unroll
        for (int nb = 0; nb < 8; nb++) {
            const int col = wn * 64 + nb * 8 + qc * 2;
            const int n = n0 + col;
            const float bv0 = bias[n];
            const float bv1 = bias[n + 1];
            #pragma unroll
            for (int half = 0; half < 2; half++) {
                const int m = m0 + wm * 32 + mb * 16 + qr + half * 8;
                const float v0 = acc[mb][nb][half*2+0] + bv0;
                const float v1 = acc[mb][nb][half*2+1] + bv1;
                if (MODE == 0) {
                    const int b = m >> 11, t = m & (Ts - 1);
                    const int which = n >> 10;
                    const int cn = n & (Cc - 1);
                    const int h = cn >> 6, d = cn & 63;
                    float* dst = (which == 0) ? g_q : (which == 1 ? g_k : g_v);
                    dst[(((size_t)(b * Hh + h) << 11) + t) * Dd + d]     = v0;
                    dst[(((size_t)(b * Hh + h) << 11) + t) * Dd + d + 1] = v1;
                } else {
                    outp[(size_t)m * N + n]     = v0;
                    outp[(size_t)m * N + n + 1] = v1;
                }
            }
        }
    }
}

// ---------------------------------------------------------------------------
// Flash attention (proven; SIMT fp32)
// ---------------------------------------------------------------------------
__global__ __launch_bounds__(256)
void attn_kernel()
{
    extern __shared__ float sm[];
    float* Qs = sm;
    float* Ks = sm + 64*68;
    float* Vs = sm + 2*64*68;
    float* Ps = sm + 3*64*68;

    const int tid = threadIdx.x;
    const int ty = tid >> 4, tx = tid & 15;
    const int qt = blockIdx.x;
    const int bh = blockIdx.y;

    const float* Qg = g_q + (size_t)bh * Ts * Dd;
    const float* Kg = g_k + (size_t)bh * Ts * Dd;
    const float* Vg = g_v + (size_t)bh * Ts * Dd;

    #pragma unroll
    for (int it = 0; it < 4; it++) {
        int idx = tid + it * 256;
        int r  = idx >> 4;
        int d4 = (idx & 15) << 2;
        float4 v = *(const float4*)(Qg + (size_t)(qt*64 + r) * Dd + d4);
        Qs[(d4+0)*68 + r] = v.x * 0.125f;
        Qs[(d4+1)*68 + r] = v.y * 0.125f;
        Qs[(d4+2)*68 + r] = v.z * 0.125f;
        Qs[(d4+3)*68 + r] = v.w * 0.125f;
    }

    float m_i[4], l_i[4], acc[4][4];
    #pragma unroll
    for (int i = 0; i < 4; i++) {
        m_i[i] = -1e30f;
        l_i[i] = 0.f;
        #pragma unroll
        for (int j = 0; j < 4; j++) acc[i][j] = 0.f;
    }

    for (int kt = 0; kt <= qt; kt++) {
        __syncthreads();
        #pragma unroll
        for (int it = 0; it < 4; it++) {
            int idx = tid + it * 256;
            int r  = idx >> 4;
            int d4 = (idx & 15) << 2;
            float4 kv = *(const float4*)(Kg + (size_t)(kt*64 + r) * Dd + d4);
            Ks[(d4+0)*68 + r] = kv.x;
            Ks[(d4+1)*68 + r] = kv.y;
            Ks[(d4+2)*68 + r] = kv.z;
            Ks[(d4+3)*68 + r] = kv.w;
            *(float4*)(&Vs[r*68 + d4]) =
                *(const float4*)(Vg + (size_t)(kt*64 + r) * Dd + d4);
        }
        __syncthreads();

        float s[4][4];
        #pragma unroll
        for (int i = 0; i < 4; i++)
            #pragma unroll
            for (int j = 0; j < 4; j++) s[i][j] = 0.f;

        #pragma unroll 4
        for (int d = 0; d < 64; d++) {
            float rq[4], rk[4];
            *(float4*)rq = *(const float4*)(Qs + d*68 + ty*4);
            *(float4*)rk = *(const float4*)(Ks + d*68 + tx*4);
            #pragma unroll
            for (int i = 0; i < 4; i++)
                #pragma unroll
                for (int j = 0; j < 4; j++)
                    s[i][j] = fmaf(rq[i], rk[j], s[i][j]);
        }

        if (kt == qt) {
            #pragma unroll
            for (int i = 0; i < 4; i++) {
                int r = ty*4 + i;
                #pragma unroll
                for (int j = 0; j < 4; j++) {
                    int cix = tx*4 + j;
                    if (cix > r) s[i][j] = -1e30f;
                }
            }
        }

        #pragma unroll
        for (int i = 0; i < 4; i++) {
            float mx = fmaxf(fmaxf(s[i][0], s[i][1]), fmaxf(s[i][2], s[i][3]));
            #pragma unroll
            for (int off = 8; off > 0; off >>= 1)
                mx = fmaxf(mx, __shfl_xor_sync(0xffffffffu, mx, off));
            float mnew = fmaxf(m_i[i], mx);
            float cf = __expf(m_i[i] - mnew);
            m_i[i] = mnew;
            float ps = 0.f;
            #pragma unroll
            for (int j = 0; j < 4; j++) {
                float p = __expf(s[i][j] - mnew);
                s[i][j] = p;
                ps += p;
            }
            #pragma unroll
            for (int off = 8; off > 0; off >>= 1)
                ps += __shfl_xor_sync(0xffffffffu, ps, off);
            l_i[i] = l_i[i] * cf + ps;
            #pragma unroll
            for (int j = 0; j < 4; j++) {
                acc[i][j] *= cf;
                Ps[(tx*4 + j)*68 + ty*4 + i] = s[i][j];
            }
        }
        __syncthreads();

        #pragma unroll 4
        for (int s0 = 0; s0 < 64; s0++) {
            float rp[4], rv[4];
            *(float4*)rp = *(const float4*)(Ps + s0*68 + ty*4);
            *(float4*)rv = *(const float4*)(Vs + s0*68 + tx*4);
            #pragma unroll
            for (int i = 0; i < 4; i++)
                #pragma unroll
                for (int j = 0; j < 4; j++)
                    acc[i][j] = fmaf(rp[i], rv[j], acc[i][j]);
        }
    }

    int b = bh >> 4, h = bh & 15;
    #pragma unroll
    for (int i = 0; i < 4; i++) {
        float inv = 1.0f / l_i[i];
        int t = qt*64 + ty*4 + i;
        #pragma unroll
        for (int j = 0; j < 4; j++) {
            int d = tx*4 + j;
            g_y[(size_t)(b * Ts + t) * Cc + h * Dd + d] = acc[i][j] * inv;
        }
    }
}

// ---------------------------------------------------------------------------
extern "C" void kernel_launch(void* const* d_in, const int* in_sizes, int n_in,
                              void* d_out, int out_size)
{
    (void)in_sizes; (void)n_in; (void)out_size;
    const float* x     = (const float*)d_in[0];
    const float* w_qkv = (const float*)d_in[1];
    const float* b_qkv = (const float*)d_in[2];
    const float* w_out = (const float*)d_in[3];
    const float* b_out = (const float*)d_in[4];
    float* out = (float*)d_out;

    cudaFuncSetAttribute(attn_kernel,
                         cudaFuncAttributeMaxDynamicSharedMemorySize,
                         4 * 64 * 68 * (int)sizeof(float));

    // 1) QKV projection (MMA, scatter epilogue). All args = harness pointers.
    gemm_mma<0, Nqkv><<<dim3(Nqkv/BN, Mtot/BM), 256>>>(x, w_qkv, b_qkv, nullptr);

    // 2) Flash attention (reads g_q/g_k/g_v, writes g_y — device refs only)
    attn_kernel<<<dim3(Ts/64, Bb*Hh), 256, 4*64*68*(int)sizeof(float)>>>();

    // 3) Output projection (MMA; A = g_y bound inside the kernel)
    gemm_mma<1, Cc><<<dim3(Cc/BN, Mtot/BM), 256>>>(nullptr, w_out, b_out, out);
}

// round 9
// speedup vs baseline: 3.7824x; 1.3200x over previous
#include <cuda_runtime.h>
#include <cuda_bf16.h>
#include <cstdint>
#include <math.h>

// Problem constants
#define Bb 4
#define Ts 2048
#define Cc 1024
#define Hh 16
#define Dd 64
#define Mtot (Bb*Ts)        // 8192
#define Nqkv (3*Cc)         // 3072
#define Kdim Cc             // 1024

// ---------------------------------------------------------------------------
// Scratch (__device__ globals). RULE: referenced ONLY from device code.
// ---------------------------------------------------------------------------
__device__ __align__(128) float g_q[Bb*Hh*Ts*Dd];
__device__ __align__(128) float g_k[Bb*Hh*Ts*Dd];
__device__ __align__(128) float g_v[Bb*Hh*Ts*Dd];
__device__ __align__(128) __nv_bfloat16 g_yhi[Mtot*Kdim];
__device__ __align__(128) __nv_bfloat16 g_ylo[Mtot*Kdim];
__device__ __align__(128) __nv_bfloat16 g_wqhi[Nqkv*Kdim];   // [N][K]
__device__ __align__(128) __nv_bfloat16 g_wqlo[Nqkv*Kdim];
__device__ __align__(128) __nv_bfloat16 g_wohi[Cc*Kdim];
__device__ __align__(128) __nv_bfloat16 g_wolo[Cc*Kdim];

// ---------------------------------------------------------------------------
// Helpers
// ---------------------------------------------------------------------------
#define MMA_BF16(c, a, b) asm volatile( \
    "mma.sync.aligned.m16n8k16.row.col.f32.bf16.bf16.f32 " \
    "{%0,%1,%2,%3}, {%4,%5,%6,%7}, {%8,%9}, {%0,%1,%2,%3};" \
    : "+f"((c)[0]), "+f"((c)[1]), "+f"((c)[2]), "+f"((c)[3]) \
    : "r"((a)[0]), "r"((a)[1]), "r"((a)[2]), "r"((a)[3]), \
      "r"((b)[0]), "r"((b)[1]))

__device__ __forceinline__ void split2(float a, __nv_bfloat16& h, __nv_bfloat16& l) {
    __nv_bfloat16 hh = __float2bfloat16(a);
    l = __float2bfloat16(a - __bfloat162float(hh));
    h = hh;
}
__device__ __forceinline__ uint32_t pack2(__nv_bfloat16 a, __nv_bfloat16 b) {
    __nv_bfloat162 p = __halves2bfloat162(a, b);
    return *(uint32_t*)&p;
}

// ---------------------------------------------------------------------------
// Weight transpose + split: in [K][N] fp32 -> device globals [N][K] bf16 hi/lo.
// MODE 0 -> g_wq*, MODE 1 -> g_wo*. Args: harness pointer only.
// ---------------------------------------------------------------------------
template<int MODE, int N>
__global__ void transpose_split_kernel(const float* __restrict__ in)
{
    __nv_bfloat16* __restrict__ hi = (MODE == 0) ? g_wqhi : g_wohi;
    __nv_bfloat16* __restrict__ lo = (MODE == 0) ? g_wqlo : g_wolo;

    __shared__ float t[32][33];
    const int n0 = blockIdx.x * 32, k0 = blockIdx.y * 32;
    #pragma unroll
    for (int i = 0; i < 4; i++) {
        int k = k0 + threadIdx.y + i * 8;
        t[threadIdx.y + i * 8][threadIdx.x] = in[(size_t)k * N + n0 + threadIdx.x];
    }
    __syncthreads();
    #pragma unroll
    for (int i = 0; i < 4; i++) {
        int n = n0 + threadIdx.y + i * 8;
        int k = k0 + threadIdx.x;
        __nv_bfloat16 h, l;
        split2(t[threadIdx.x][threadIdx.y + i * 8], h, l);
        hi[(size_t)n * Kdim + k] = h;
        lo[(size_t)n * Kdim + k] = l;
    }
}

#define BM 128
#define BN 128
#define BK 32
#define KPAD 40

// ---------------------------------------------------------------------------
// 3xBF16 warp-MMA GEMM (compute core = round-8-proven).
// MODE 0: A = x (param, fp32, in-kernel split), B = g_wq*, scatter epilogue.
// MODE 1: A = g_y{hi,lo} (bf16 globals), B = g_wo*, linear epilogue -> outp.
// B/A(bf16) smem fills are coalesced uint4 (the round-8 L1 fix).
// ---------------------------------------------------------------------------
template<int MODE, int N>
__global__ __launch_bounds__(256)
void gemm_mma(const float* __restrict__ Ap,
              const float* __restrict__ bias,
              float* __restrict__ outp)
{
    const __nv_bfloat16* __restrict__ Bhi = (MODE == 0) ? g_wqhi : g_wohi;
    const __nv_bfloat16* __restrict__ Blo = (MODE == 0) ? g_wqlo : g_wolo;

    __shared__ __align__(16) __nv_bfloat16 sA[2][BM * KPAD];
    __shared__ __align__(16) __nv_bfloat16 sB[2][BN * KPAD];

    const int tid = threadIdx.x;
    const int l = tid & 31;
    const int wid = tid >> 5;
    const int wm = wid & 3;
    const int wn = wid >> 2;
    const int m0 = blockIdx.y * BM;
    const int n0 = blockIdx.x * BN;
    const int qr = l >> 2;
    const int qc = l & 3;

    float acc[2][8][4];
    #pragma unroll
    for (int i = 0; i < 2; i++)
        #pragma unroll
        for (int j = 0; j < 8; j++)
            #pragma unroll
            for (int q = 0; q < 4; q++) acc[i][j][q] = 0.f;

    // fp32 A-split mapping (MODE 0, proven)
    const int arw = tid >> 3;
    const int acl = (tid & 7) * 4;
    // bf16 uint4 fill mapping (B always; A in MODE 1)
    const int fr = tid >> 2;           // 0..63 (+64)
    const int fs = (tid & 3) * 8;      // bf16 offset 0,8,16,24

    for (int kc = 0; kc < Kdim / BK; kc++) {
        const int k0 = kc * BK;
        __syncthreads();

        if (MODE == 0) {
            #pragma unroll
            for (int pass = 0; pass < 4; pass++) {
                const int r = arw + pass * 32;
                float4 av = *(const float4*)&Ap[(size_t)(m0 + r) * Kdim + k0 + acl];
                __nv_bfloat16 h0,l0,h1,l1,h2,l2,h3,l3;
                split2(av.x, h0, l0); split2(av.y, h1, l1);
                split2(av.z, h2, l2); split2(av.w, h3, l3);
                *(uint32_t*)&sA[0][r * KPAD + acl]     = pack2(h0, h1);
                *(uint32_t*)&sA[0][r * KPAD + acl + 2] = pack2(h2, h3);
                *(uint32_t*)&sA[1][r * KPAD + acl]     = pack2(l0, l1);
                *(uint32_t*)&sA[1][r * KPAD + acl + 2] = pack2(l2, l3);
            }
        } else {
            #pragma unroll
            for (int hx = 0; hx < 2; hx++) {
                const int r = fr + hx * 64;
                const size_t ga = (size_t)(m0 + r) * Kdim + k0 + fs;
                *(uint4*)&sA[0][r * KPAD + fs] = *(const uint4*)&g_yhi[ga];
                *(uint4*)&sA[1][r * KPAD + fs] = *(const uint4*)&g_ylo[ga];
            }
        }
        // B: coalesced uint4 from pre-split [N][K] bf16
        #pragma unroll
        for (int hx = 0; hx < 2; hx++) {
            const int r = fr + hx * 64;
            const size_t gb = (size_t)(n0 + r) * Kdim + k0 + fs;
            *(uint4*)&sB[0][r * KPAD + fs] = *(const uint4*)&Bhi[gb];
            *(uint4*)&sB[1][r * KPAD + fs] = *(const uint4*)&Blo[gb];
        }
        __syncthreads();

        #pragma unroll
        for (int kk = 0; kk < 2; kk++) {
            const int kb = kk * 16 + qc * 2;
            uint32_t bh[8][2], bl[8][2];
            #pragma unroll
            for (int nb = 0; nb < 8; nb++) {
                const int nrow = wn * 64 + nb * 8 + qr;
                bh[nb][0] = *(const uint32_t*)&sB[0][nrow * KPAD + kb];
                bh[nb][1] = *(const uint32_t*)&sB[0][nrow * KPAD + kb + 8];
                bl[nb][0] = *(const uint32_t*)&sB[1][nrow * KPAD + kb];
                bl[nb][1] = *(const uint32_t*)&sB[1][nrow * KPAD + kb + 8];
            }
            #pragma unroll
            for (int mb = 0; mb < 2; mb++) {
                const int arow = wm * 32 + mb * 16 + qr;
                uint32_t ah[4], al[4];
                ah[0] = *(const uint32_t*)&sA[0][arow * KPAD + kb];
                ah[1] = *(const uint32_t*)&sA[0][(arow + 8) * KPAD + kb];
                ah[2] = *(const uint32_t*)&sA[0][arow * KPAD + kb + 8];
                ah[3] = *(const uint32_t*)&sA[0][(arow + 8) * KPAD + kb + 8];
                al[0] = *(const uint32_t*)&sA[1][arow * KPAD + kb];
                al[1] = *(const uint32_t*)&sA[1][(arow + 8) * KPAD + kb];
                al[2] = *(const uint32_t*)&sA[1][arow * KPAD + kb + 8];
                al[3] = *(const uint32_t*)&sA[1][(arow + 8) * KPAD + kb + 8];
                #pragma unroll
                for (int nb = 0; nb < 8; nb++) {
                    MMA_BF16(acc[mb][nb], ah, bh[nb]);
                    MMA_BF16(acc[mb][nb], ah, bl[nb]);
                    MMA_BF16(acc[mb][nb], al, bh[nb]);
                }
            }
        }
    }

    // ---- epilogue (proven) ----
    #pragma unroll
    for (int mb = 0; mb < 2; mb++) {
        #pragma unroll
        for (int nb = 0; nb < 8; nb++) {
            const int col = wn * 64 + nb * 8 + qc * 2;
            const int n = n0 + col;
            const float bv0 = bias[n];
            const float bv1 = bias[n + 1];
            #pragma unroll
            for (int half = 0; half < 2; half++) {
                const int m = m0 + wm * 32 + mb * 16 + qr + half * 8;
                const float v0 = acc[mb][nb][half*2+0] + bv0;
                const float v1 = acc[mb][nb][half*2+1] + bv1;
                if (MODE == 0) {
                    const int b = m >> 11, t = m & (Ts - 1);
                    const int which = n >> 10;
                    const int cn = n & (Cc - 1);
                    const int h = cn >> 6, d = cn & 63;
                    float* dst = (which == 0) ? g_q : (which == 1 ? g_k : g_v);
                    dst[(((size_t)(b * Hh + h) << 11) + t) * Dd + d]     = v0;
                    dst[(((size_t)(b * Hh + h) << 11) + t) * Dd + d + 1] = v1;
                } else {
                    outp[(size_t)m * N + n]     = v0;
                    outp[(size_t)m * N + n + 1] = v1;
                }
            }
        }
    }
}

// ---------------------------------------------------------------------------
// Flash attention (proven core); epilogue now writes g_yhi/g_ylo bf16 split.
// ---------------------------------------------------------------------------
__global__ __launch_bounds__(256)
void attn_kernel()
{
    extern __shared__ float sm[];
    float* Qs = sm;
    float* Ks = sm + 64*68;
    float* Vs = sm + 2*64*68;
    float* Ps = sm + 3*64*68;

    const int tid = threadIdx.x;
    const int ty = tid >> 4, tx = tid & 15;
    const int qt = blockIdx.x;
    const int bh = blockIdx.y;

    const float* Qg = g_q + (size_t)bh * Ts * Dd;
    const float* Kg = g_k + (size_t)bh * Ts * Dd;
    const float* Vg = g_v + (size_t)bh * Ts * Dd;

    #pragma unroll
    for (int it = 0; it < 4; it++) {
        int idx = tid + it * 256;
        int r  = idx >> 4;
        int d4 = (idx & 15) << 2;
        float4 v = *(const float4*)(Qg + (size_t)(qt*64 + r) * Dd + d4);
        Qs[(d4+0)*68 + r] = v.x * 0.125f;
        Qs[(d4+1)*68 + r] = v.y * 0.125f;
        Qs[(d4+2)*68 + r] = v.z * 0.125f;
        Qs[(d4+3)*68 + r] = v.w * 0.125f;
    }

    float m_i[4], l_i[4], acc[4][4];
    #pragma unroll
    for (int i = 0; i < 4; i++) {
        m_i[i] = -1e30f;
        l_i[i] = 0.f;
        #pragma unroll
        for (int j = 0; j < 4; j++) acc[i][j] = 0.f;
    }

    for (int kt = 0; kt <= qt; kt++) {
        __syncthreads();
        #pragma unroll
        for (int it = 0; it < 4; it++) {
            int idx = tid + it * 256;
            int r  = idx >> 4;
            int d4 = (idx & 15) << 2;
            float4 kv = *(const float4*)(Kg + (size_t)(kt*64 + r) * Dd + d4);
            Ks[(d4+0)*68 + r] = kv.x;
            Ks[(d4+1)*68 + r] = kv.y;
            Ks[(d4+2)*68 + r] = kv.z;
            Ks[(d4+3)*68 + r] = kv.w;
            *(float4*)(&Vs[r*68 + d4]) =
                *(const float4*)(Vg + (size_t)(kt*64 + r) * Dd + d4);
        }
        __syncthreads();

        float s[4][4];
        #pragma unroll
        for (int i = 0; i < 4; i++)
            #pragma unroll
            for (int j = 0; j < 4; j++) s[i][j] = 0.f;

        #pragma unroll 4
        for (int d = 0; d < 64; d++) {
            float rq[4], rk[4];
            *(float4*)rq = *(const float4*)(Qs + d*68 + ty*4);
            *(float4*)rk = *(const float4*)(Ks + d*68 + tx*4);
            #pragma unroll
            for (int i = 0; i < 4; i++)
                #pragma unroll
                for (int j = 0; j < 4; j++)
                    s[i][j] = fmaf(rq[i], rk[j], s[i][j]);
        }

        if (kt == qt) {
            #pragma unroll
            for (int i = 0; i < 4; i++) {
                int r = ty*4 + i;
                #pragma unroll
                for (int j = 0; j < 4; j++) {
                    int cix = tx*4 + j;
                    if (cix > r) s[i][j] = -1e30f;
                }
            }
        }

        #pragma unroll
        for (int i = 0; i < 4; i++) {
            float mx = fmaxf(fmaxf(s[i][0], s[i][1]), fmaxf(s[i][2], s[i][3]));
            #pragma unroll
            for (int off = 8; off > 0; off >>= 1)
                mx = fmaxf(mx, __shfl_xor_sync(0xffffffffu, mx, off));
            float mnew = fmaxf(m_i[i], mx);
            float cf = __expf(m_i[i] - mnew);
            m_i[i] = mnew;
            float ps = 0.f;
            #pragma unroll
            for (int j = 0; j < 4; j++) {
                float p = __expf(s[i][j] - mnew);
                s[i][j] = p;
                ps += p;
            }
            #pragma unroll
            for (int off = 8; off > 0; off >>= 1)
                ps += __shfl_xor_sync(0xffffffffu, ps, off);
            l_i[i] = l_i[i] * cf + ps;
            #pragma unroll
            for (int j = 0; j < 4; j++) {
                acc[i][j] *= cf;
                Ps[(tx*4 + j)*68 + ty*4 + i] = s[i][j];
            }
        }
        __syncthreads();

        #pragma unroll 4
        for (int s0 = 0; s0 < 64; s0++) {
            float rp[4], rv[4];
            *(float4*)rp = *(const float4*)(Ps + s0*68 + ty*4);
            *(float4*)rv = *(const float4*)(Vs + s0*68 + tx*4);
            #pragma unroll
            for (int i = 0; i < 4; i++)
                #pragma unroll
                for (int j = 0; j < 4; j++)
                    acc[i][j] = fmaf(rp[i], rv[j], acc[i][j]);
        }
    }

    int b = bh >> 4, h = bh & 15;
    #pragma unroll
    for (int i = 0; i < 4; i++) {
        float inv = 1.0f / l_i[i];
        int t = qt*64 + ty*4 + i;
        #pragma unroll
        for (int j = 0; j < 4; j++) {
            int d = tx*4 + j;
            const size_t idx = (size_t)(b * Ts + t) * Cc + h * Dd + d;
            __nv_bfloat16 yh, yl;
            split2(acc[i][j] * inv, yh, yl);
            g_yhi[idx] = yh;
            g_ylo[idx] = yl;
        }
    }
}

// ---------------------------------------------------------------------------
extern "C" void kernel_launch(void* const* d_in, const int* in_sizes, int n_in,
                              void* d_out, int out_size)
{
    (void)in_sizes; (void)n_in; (void)out_size;
    const float* x     = (const float*)d_in[0];
    const float* w_qkv = (const float*)d_in[1];
    const float* b_qkv = (const float*)d_in[2];
    const float* w_out = (const float*)d_in[3];
    const float* b_out = (const float*)d_in[4];
    float* out = (float*)d_out;

    cudaFuncSetAttribute(attn_kernel,
                         cudaFuncAttributeMaxDynamicSharedMemorySize,
                         4 * 64 * 68 * (int)sizeof(float));

    // 0) Pre-split weights into [N][K] bf16 hi/lo device globals
    transpose_split_kernel<0, Nqkv><<<dim3(Nqkv/32, Kdim/32), dim3(32,8)>>>(w_qkv);
    transpose_split_kernel<1, Cc><<<dim3(Cc/32, Kdim/32), dim3(32,8)>>>(w_out);

    // 1) QKV projection (MMA) + scatter
    gemm_mma<0, Nqkv><<<dim3(Nqkv/BN, Mtot/BM), 256>>>(x, b_qkv, nullptr);

    // 2) Flash attention (writes g_yhi/g_ylo)
    attn_kernel<<<dim3(Ts/64, Bb*Hh), 256, 4*64*68*(int)sizeof(float)>>>();

    // 3) Output projection (MMA) -> out
    gemm_mma<1, Cc><<<dim3(Cc/BN, Mtot/BM), 256>>>(nullptr, b_out, out);
}

// round 11
// speedup vs baseline: 6.3161x; 1.6699x over previous
#include <cuda_runtime.h>
#include <cuda_bf16.h>
#include <cstdint>
#include <math.h>

// Problem constants
#define Bb 4
#define Ts 2048
#define Cc 1024
#define Hh 16
#define Dd 64
#define Mtot (Bb*Ts)        // 8192
#define Nqkv (3*Cc)         // 3072
#define Kdim Cc             // 1024

// ---------------------------------------------------------------------------
// Scratch (__device__ globals). RULE: referenced ONLY from device code.
// ---------------------------------------------------------------------------
__device__ __align__(128) __nv_bfloat16 g_qhi[Bb*Hh*Ts*Dd];  // [b,h,t,d], pre-scaled 1/8
__device__ __align__(128) __nv_bfloat16 g_qlo[Bb*Hh*Ts*Dd];
__device__ __align__(128) __nv_bfloat16 g_khi[Bb*Hh*Ts*Dd];  // [b,h,t,d]
__device__ __align__(128) __nv_bfloat16 g_klo[Bb*Hh*Ts*Dd];
__device__ __align__(128) __nv_bfloat16 g_vthi[Bb*Hh*Dd*Ts]; // [b,h,d,t] (transposed)
__device__ __align__(128) __nv_bfloat16 g_vtlo[Bb*Hh*Dd*Ts];
__device__ __align__(128) __nv_bfloat16 g_yhi[Mtot*Kdim];
__device__ __align__(128) __nv_bfloat16 g_ylo[Mtot*Kdim];
__device__ __align__(128) __nv_bfloat16 g_wqhi[Nqkv*Kdim];   // [N][K]
__device__ __align__(128) __nv_bfloat16 g_wqlo[Nqkv*Kdim];
__device__ __align__(128) __nv_bfloat16 g_wohi[Cc*Kdim];
__device__ __align__(128) __nv_bfloat16 g_wolo[Cc*Kdim];

// ---------------------------------------------------------------------------
// Helpers
// ---------------------------------------------------------------------------
#define MMA_BF16(c, a, b) asm volatile( \
    "mma.sync.aligned.m16n8k16.row.col.f32.bf16.bf16.f32 " \
    "{%0,%1,%2,%3}, {%4,%5,%6,%7}, {%8,%9}, {%0,%1,%2,%3};" \
    : "+f"((c)[0]), "+f"((c)[1]), "+f"((c)[2]), "+f"((c)[3]) \
    : "r"((a)[0]), "r"((a)[1]), "r"((a)[2]), "r"((a)[3]), \
      "r"((b)[0]), "r"((b)[1]))

__device__ __forceinline__ void split2(float a, __nv_bfloat16& h, __nv_bfloat16& l) {
    __nv_bfloat16 hh = __float2bfloat16(a);
    l = __float2bfloat16(a - __bfloat162float(hh));
    h = hh;
}
__device__ __forceinline__ uint32_t pack2(__nv_bfloat16 a, __nv_bfloat16 b) {
    __nv_bfloat162 p = __halves2bfloat162(a, b);
    return *(uint32_t*)&p;
}

// ---------------------------------------------------------------------------
// Weight transpose + split (proven)
// ---------------------------------------------------------------------------
template<int MODE, int N>
__global__ void transpose_split_kernel(const float* __restrict__ in)
{
    __nv_bfloat16* __restrict__ hi = (MODE == 0) ? g_wqhi : g_wohi;
    __nv_bfloat16* __restrict__ lo = (MODE == 0) ? g_wqlo : g_wolo;

    __shared__ float t[32][33];
    const int n0 = blockIdx.x * 32, k0 = blockIdx.y * 32;
    #pragma unroll
    for (int i = 0; i < 4; i++) {
        int k = k0 + threadIdx.y + i * 8;
        t[threadIdx.y + i * 8][threadIdx.x] = in[(size_t)k * N + n0 + threadIdx.x];
    }
    __syncthreads();
    #pragma unroll
    for (int i = 0; i < 4; i++) {
        int n = n0 + threadIdx.y + i * 8;
        int k = k0 + threadIdx.x;
        __nv_bfloat16 h, l;
        split2(t[threadIdx.x][threadIdx.y + i * 8], h, l);
        hi[(size_t)n * Kdim + k] = h;
        lo[(size_t)n * Kdim + k] = l;
    }
}

#define BM 128
#define BN 128
#define BK 32
#define KPAD 40

// ---------------------------------------------------------------------------
// 3xBF16 warp-MMA GEMM (proven core).
// MODE 0: A = x (fp32, in-kernel split), B = g_wq*; epilogue splits+scatters
//         q (x0.125) / k -> [b,h,t,d] bf16 hi/lo, v -> [b,h,d,t] transposed.
// MODE 1: A = g_y{hi,lo}, B = g_wo*; epilogue -> outp fp32.
// ---------------------------------------------------------------------------
template<int MODE, int N>
__global__ __launch_bounds__(256)
void gemm_mma(const float* __restrict__ Ap,
              const float* __restrict__ bias,
              float* __restrict__ outp)
{
    const __nv_bfloat16* __restrict__ Bhi = (MODE == 0) ? g_wqhi : g_wohi;
    const __nv_bfloat16* __restrict__ Blo = (MODE == 0) ? g_wqlo : g_wolo;

    __shared__ __align__(16) __nv_bfloat16 sA[2][BM * KPAD];
    __shared__ __align__(16) __nv_bfloat16 sB[2][BN * KPAD];

    const int tid = threadIdx.x;
    const int l = tid & 31;
    const int wid = tid >> 5;
    const int wm = wid & 3;
    const int wn = wid >> 2;
    const int m0 = blockIdx.y * BM;
    const int n0 = blockIdx.x * BN;
    const int qr = l >> 2;
    const int qc = l & 3;

    float acc[2][8][4];
    #pragma unroll
    for (int i = 0; i < 2; i++)
        #pragma unroll
        for (int j = 0; j < 8; j++)
            #pragma unroll
            for (int q = 0; q < 4; q++) acc[i][j][q] = 0.f;

    const int arw = tid >> 3;
    const int acl = (tid & 7) * 4;
    const int fr = tid >> 2;
    const int fs = (tid & 3) * 8;

    for (int kc = 0; kc < Kdim / BK; kc++) {
        const int k0 = kc * BK;
        __syncthreads();

        if (MODE == 0) {
            #pragma unroll
            for (int pass = 0; pass < 4; pass++) {
                const int r = arw + pass * 32;
                float4 av = *(const float4*)&Ap[(size_t)(m0 + r) * Kdim + k0 + acl];
                __nv_bfloat16 h0,l0,h1,l1,h2,l2,h3,l3;
                split2(av.x, h0, l0); split2(av.y, h1, l1);
                split2(av.z, h2, l2); split2(av.w, h3, l3);
                *(uint32_t*)&sA[0][r * KPAD + acl]     = pack2(h0, h1);
                *(uint32_t*)&sA[0][r * KPAD + acl + 2] = pack2(h2, h3);
                *(uint32_t*)&sA[1][r * KPAD + acl]     = pack2(l0, l1);
                *(uint32_t*)&sA[1][r * KPAD + acl + 2] = pack2(l2, l3);
            }
        } else {
            #pragma unroll
            for (int hx = 0; hx < 2; hx++) {
                const int r = fr + hx * 64;
                const size_t ga = (size_t)(m0 + r) * Kdim + k0 + fs;
                *(uint4*)&sA[0][r * KPAD + fs] = *(const uint4*)&g_yhi[ga];
                *(uint4*)&sA[1][r * KPAD + fs] = *(const uint4*)&g_ylo[ga];
            }
        }
        #pragma unroll
        for (int hx = 0; hx < 2; hx++) {
            const int r = fr + hx * 64;
            const size_t gb = (size_t)(n0 + r) * Kdim + k0 + fs;
            *(uint4*)&sB[0][r * KPAD + fs] = *(const uint4*)&Bhi[gb];
            *(uint4*)&sB[1][r * KPAD + fs] = *(const uint4*)&Blo[gb];
        }
        __syncthreads();

        #pragma unroll
        for (int kk = 0; kk < 2; kk++) {
            const int kb = kk * 16 + qc * 2;
            uint32_t bh[8][2], bl[8][2];
            #pragma unroll
            for (int nb = 0; nb < 8; nb++) {
                const int nrow = wn * 64 + nb * 8 + qr;
                bh[nb][0] = *(const uint32_t*)&sB[0][nrow * KPAD + kb];
                bh[nb][1] = *(const uint32_t*)&sB[0][nrow * KPAD + kb + 8];
                bl[nb][0] = *(const uint32_t*)&sB[1][nrow * KPAD + kb];
                bl[nb][1] = *(const uint32_t*)&sB[1][nrow * KPAD + kb + 8];
            }
            #pragma unroll
            for (int mb = 0; mb < 2; mb++) {
                const int arow = wm * 32 + mb * 16 + qr;
                uint32_t ah[4], al[4];
                ah[0] = *(const uint32_t*)&sA[0][arow * KPAD + kb];
                ah[1] = *(const uint32_t*)&sA[0][(arow + 8) * KPAD + kb];
                ah[2] = *(const uint32_t*)&sA[0][arow * KPAD + kb + 8];
                ah[3] = *(const uint32_t*)&sA[0][(arow + 8) * KPAD + kb + 8];
                al[0] = *(const uint32_t*)&sA[1][arow * KPAD + kb];
                al[1] = *(const uint32_t*)&sA[1][(arow + 8) * KPAD + kb];
                al[2] = *(const uint32_t*)&sA[1][arow * KPAD + kb + 8];
                al[3] = *(const uint32_t*)&sA[1][(arow + 8) * KPAD + kb + 8];
                #pragma unroll
                for (int nb = 0; nb < 8; nb++) {
                    MMA_BF16(acc[mb][nb], ah, bh[nb]);
                    MMA_BF16(acc[mb][nb], ah, bl[nb]);
                    MMA_BF16(acc[mb][nb], al, bh[nb]);
                }
            }
        }
    }

    // ---- epilogue ----
    #pragma unroll
    for (int mb = 0; mb < 2; mb++) {
        #pragma unroll
        for (int nb = 0; nb < 8; nb++) {
            const int col = wn * 64 + nb * 8 + qc * 2;
            const int n = n0 + col;
            const float bv0 = bias[n];
            const float bv1 = bias[n + 1];
            #pragma unroll
            for (int half = 0; half < 2; half++) {
                const int m = m0 + wm * 32 + mb * 16 + qr + half * 8;
                float v0 = acc[mb][nb][half*2+0] + bv0;
                float v1 = acc[mb][nb][half*2+1] + bv1;
                if (MODE == 0) {
                    const int b = m >> 11, t = m & (Ts - 1);
                    const int which = n >> 10;
                    const int cn = n & (Cc - 1);
                    const int h = cn >> 6, d = cn & 63;
                    const size_t bh_ = (size_t)(b * Hh + h);
                    __nv_bfloat16 h0, l0, h1, l1;
                    if (which == 0) {           // Q: fold in 1/8 (exact pow2)
                        split2(v0 * 0.125f, h0, l0);
                        split2(v1 * 0.125f, h1, l1);
                        const size_t idx = (bh_ * Ts + t) * Dd + d;
                        *(uint32_t*)&g_qhi[idx] = pack2(h0, h1);
                        *(uint32_t*)&g_qlo[idx] = pack2(l0, l1);
                    } else if (which == 1) {    // K
                        split2(v0, h0, l0);
                        split2(v1, h1, l1);
                        const size_t idx = (bh_ * Ts + t) * Dd + d;
                        *(uint32_t*)&g_khi[idx] = pack2(h0, h1);
                        *(uint32_t*)&g_klo[idx] = pack2(l0, l1);
                    } else {                    // V: transposed [d][t]
                        split2(v0, h0, l0);
                        split2(v1, h1, l1);
                        const size_t i0 = (bh_ * Dd + d) * Ts + t;
                        const size_t i1 = (bh_ * Dd + d + 1) * Ts + t;
                        g_vthi[i0] = h0; g_vtlo[i0] = l0;
                        g_vthi[i1] = h1; g_vtlo[i1] = l1;
                    }
                } else {
                    outp[(size_t)m * N + n]     = v0;
                    outp[(size_t)m * N + n + 1] = v1;
                }
            }
        }
    }
}

// ---------------------------------------------------------------------------
// MMA flash attention: 128 threads = 4 warps x 16 Q-rows; 64-key tiles.
// S = Q@K^T and O += P@V both on the proven 3xbf16 m16n8k16 core.
// ---------------------------------------------------------------------------
#define SPAD 72

__global__ __launch_bounds__(128)
void attn_kernel()
{
    __shared__ __align__(16) __nv_bfloat16 sKh[64 * SPAD];
    __shared__ __align__(16) __nv_bfloat16 sKl[64 * SPAD];
    __shared__ __align__(16) __nv_bfloat16 sVh[64 * SPAD];  // V^T: [d][t]
    __shared__ __align__(16) __nv_bfloat16 sVl[64 * SPAD];

    const int tid = threadIdx.x;
    const int l = tid & 31;
    const int wm = tid >> 5;          // warp -> 16 Q-rows
    const int qr = l >> 2;
    const int qc = l & 3;
    const int qt = blockIdx.x;        // Q tile (64 rows)
    const int bh = blockIdx.y;

    const size_t qk_base = (size_t)bh * Ts * Dd;
    const size_t vt_base = (size_t)bh * Dd * Ts;

    // ---- Q fragments (registers, loaded once) ----
    uint32_t qh[4][4], ql[4][4];
    {
        const int r0 = qt * 64 + wm * 16 + qr;
        #pragma unroll
        for (int ks = 0; ks < 4; ks++) {
            const int kcol = ks * 16 + qc * 2;
            qh[ks][0] = *(const uint32_t*)&g_qhi[qk_base + (size_t)r0 * Dd + kcol];
            qh[ks][1] = *(const uint32_t*)&g_qhi[qk_base + (size_t)(r0 + 8) * Dd + kcol];
            qh[ks][2] = *(const uint32_t*)&g_qhi[qk_base + (size_t)r0 * Dd + kcol + 8];
            qh[ks][3] = *(const uint32_t*)&g_qhi[qk_base + (size_t)(r0 + 8) * Dd + kcol + 8];
            ql[ks][0] = *(const uint32_t*)&g_qlo[qk_base + (size_t)r0 * Dd + kcol];
            ql[ks][1] = *(const uint32_t*)&g_qlo[qk_base + (size_t)(r0 + 8) * Dd + kcol];
            ql[ks][2] = *(const uint32_t*)&g_qlo[qk_base + (size_t)r0 * Dd + kcol + 8];
            ql[ks][3] = *(const uint32_t*)&g_qlo[qk_base + (size_t)(r0 + 8) * Dd + kcol + 8];
        }
    }

    float o[8][4];
    #pragma unroll
    for (int i = 0; i < 8; i++)
        #pragma unroll
        for (int j = 0; j < 4; j++) o[i][j] = 0.f;
    float m0v = -1e30f, m1v = -1e30f, l0v = 0.f, l1v = 0.f;

    for (int kt = 0; kt <= qt; kt++) {
        __syncthreads();
        // ---- fill K and V^T tiles (coalesced uint4) ----
        for (int i = tid; i < 512; i += 128) {
            const int row = i >> 3;
            const int seg = (i & 7) * 8;
            const size_t gk = qk_base + (size_t)(kt * 64 + row) * Dd + seg;
            *(uint4*)&sKh[row * SPAD + seg] = *(const uint4*)&g_khi[gk];
            *(uint4*)&sKl[row * SPAD + seg] = *(const uint4*)&g_klo[gk];
            const size_t gv = vt_base + (size_t)row * Ts + kt * 64 + seg;
            *(uint4*)&sVh[row * SPAD + seg] = *(const uint4*)&g_vthi[gv];
            *(uint4*)&sVl[row * SPAD + seg] = *(const uint4*)&g_vtlo[gv];
        }
        __syncthreads();

        // ---- S = Q K^T ----
        float c[8][4];
        #pragma unroll
        for (int nb = 0; nb < 8; nb++)
            #pragma unroll
            for (int q = 0; q < 4; q++) c[nb][q] = 0.f;

        #pragma unroll
        for (int ks = 0; ks < 4; ks++) {
            const int kb = ks * 16 + qc * 2;
            #pragma unroll
            for (int nb = 0; nb < 8; nb++) {
                const int nrow = nb * 8 + qr;
                uint32_t bhf[2], blf[2];
                bhf[0] = *(const uint32_t*)&sKh[nrow * SPAD + kb];
                bhf[1] = *(const uint32_t*)&sKh[nrow * SPAD + kb + 8];
                blf[0] = *(const uint32_t*)&sKl[nrow * SPAD + kb];
                blf[1] = *(const uint32_t*)&sKl[nrow * SPAD + kb + 8];
                MMA_BF16(c[nb], qh[ks], bhf);
                MMA_BF16(c[nb], qh[ks], blf);
                MMA_BF16(c[nb], ql[ks], bhf);
            }
        }

        // ---- causal mask on diagonal tile ----
        if (kt == qt) {
            const int r0 = qt * 64 + wm * 16 + qr;
            #pragma unroll
            for (int nb = 0; nb < 8; nb++) {
                const int col = kt * 64 + nb * 8 + qc * 2;
                if (col > r0)     c[nb][0] = -1e30f;
                if (col + 1 > r0) c[nb][1] = -1e30f;
                if (col > r0 + 8)     c[nb][2] = -1e30f;
                if (col + 1 > r0 + 8) c[nb][3] = -1e30f;
            }
        }

        // ---- online softmax (rows qr and qr+8) ----
        float rmax0 = -1e30f, rmax1 = -1e30f;
        #pragma unroll
        for (int nb = 0; nb < 8; nb++) {
            rmax0 = fmaxf(rmax0, fmaxf(c[nb][0], c[nb][1]));
            rmax1 = fmaxf(rmax1, fmaxf(c[nb][2], c[nb][3]));
        }
        #pragma unroll
        for (int off = 1; off <= 2; off <<= 1) {
            rmax0 = fmaxf(rmax0, __shfl_xor_sync(0xffffffffu, rmax0, off));
            rmax1 = fmaxf(rmax1, __shfl_xor_sync(0xffffffffu, rmax1, off));
        }
        const float mn0 = fmaxf(m0v, rmax0);
        const float mn1 = fmaxf(m1v, rmax1);
        const float cf0 = __expf(m0v - mn0);
        const float cf1 = __expf(m1v - mn1);
        m0v = mn0; m1v = mn1;

        float s0 = 0.f, s1 = 0.f;
        #pragma unroll
        for (int nb = 0; nb < 8; nb++) {
            c[nb][0] = __expf(c[nb][0] - mn0); s0 += c[nb][0];
            c[nb][1] = __expf(c[nb][1] - mn0); s0 += c[nb][1];
            c[nb][2] = __expf(c[nb][2] - mn1); s1 += c[nb][2];
            c[nb][3] = __expf(c[nb][3] - mn1); s1 += c[nb][3];
        }
        #pragma unroll
        for (int off = 1; off <= 2; off <<= 1) {
            s0 += __shfl_xor_sync(0xffffffffu, s0, off);
            s1 += __shfl_xor_sync(0xffffffffu, s1, off);
        }
        l0v = l0v * cf0 + s0;
        l1v = l1v * cf1 + s1;
        #pragma unroll
        for (int i = 0; i < 8; i++) {
            o[i][0] *= cf0; o[i][1] *= cf0;
            o[i][2] *= cf1; o[i][3] *= cf1;
        }

        // ---- P fragments in-register (C-layout -> A-layout), hi/lo split ----
        uint32_t ph[4][4], pl[4][4];
        #pragma unroll
        for (int ks2 = 0; ks2 < 4; ks2++) {
            #pragma unroll
            for (int part = 0; part < 4; part++) {
                const int nb = 2 * ks2 + (part >> 1);      // part 0,1 -> nb even; 2,3 -> odd
                const int base = (part & 1) * 2;           // c0c1 (row qr) or c2c3 (row qr+8)
                // A-frag order: a0=(r,k0) a1=(r+8,k0) a2=(r,k0+8) a3=(r+8,k0+8)
                const int aidx = (part >> 1) * 2 + (part & 1);
                const float v0 = c[nb][base + 0];
                const float v1 = c[nb][base + 1];
                __nv_bfloat16 h0, lo0, h1, lo1;
                split2(v0, h0, lo0);
                split2(v1, h1, lo1);
                ph[ks2][aidx] = pack2(h0, h1);
                pl[ks2][aidx] = pack2(lo0, lo1);
            }
        }

        // ---- O += P @ V (V^T in smem as B operand) ----
        #pragma unroll
        for (int ks2 = 0; ks2 < 4; ks2++) {
            const int kb = ks2 * 16 + qc * 2;
            #pragma unroll
            for (int nb2 = 0; nb2 < 8; nb2++) {
                const int nrow = nb2 * 8 + qr;
                uint32_t vhf[2], vlf[2];
                vhf[0] = *(const uint32_t*)&sVh[nrow * SPAD + kb];
                vhf[1] = *(const uint32_t*)&sVh[nrow * SPAD + kb + 8];
                vlf[0] = *(const uint32_t*)&sVl[nrow * SPAD + kb];
                vlf[1] = *(const uint32_t*)&sVl[nrow * SPAD + kb + 8];
                MMA_BF16(o[nb2], ph[ks2], vhf);
                MMA_BF16(o[nb2], ph[ks2], vlf);
                MMA_BF16(o[nb2], pl[ks2], vhf);
            }
        }
    }

    // ---- epilogue: normalize, split, write g_yhi/g_ylo ----
    const int b = bh >> 4, h = bh & 15;
    const float inv0 = 1.0f / l0v;
    const float inv1 = 1.0f / l1v;
    const int t0 = qt * 64 + wm * 16 + qr;
    #pragma unroll
    for (int nb2 = 0; nb2 < 8; nb2++) {
        const int d = nb2 * 8 + qc * 2;
        {
            const size_t idx = (size_t)(b * Ts + t0) * Cc + h * Dd + d;
            __nv_bfloat16 h0, lo0, h1, lo1;
            split2(o[nb2][0] * inv0, h0, lo0);
            split2(o[nb2][1] * inv0, h1, lo1);
            *(uint32_t*)&g_yhi[idx] = pack2(h0, h1);
            *(uint32_t*)&g_ylo[idx] = pack2(lo0, lo1);
        }
        {
            const size_t idx = (size_t)(b * Ts + t0 + 8) * Cc + h * Dd + d;
            __nv_bfloat16 h0, lo0, h1, lo1;
            split2(o[nb2][2] * inv1, h0, lo0);
            split2(o[nb2][3] * inv1, h1, lo1);
            *(uint32_t*)&g_yhi[idx] = pack2(h0, h1);
            *(uint32_t*)&g_ylo[idx] = pack2(lo0, lo1);
        }
    }
}

// ---------------------------------------------------------------------------
extern "C" void kernel_launch(void* const* d_in, const int* in_sizes, int n_in,
                              void* d_out, int out_size)
{
    (void)in_sizes; (void)n_in; (void)out_size;
    const float* x     = (const float*)d_in[0];
    const float* w_qkv = (const float*)d_in[1];
    const float* b_qkv = (const float*)d_in[2];
    const float* w_out = (const float*)d_in[3];
    const float* b_out = (const float*)d_in[4];
    float* out = (float*)d_out;

    // 0) Pre-split weights into [N][K] bf16 hi/lo device globals
    transpose_split_kernel<0, Nqkv><<<dim3(Nqkv/32, Kdim/32), dim3(32,8)>>>(w_qkv);
    transpose_split_kernel<1, Cc><<<dim3(Cc/32, Kdim/32), dim3(32,8)>>>(w_out);

    // 1) QKV projection (MMA) -> bf16 hi/lo q/k/v^T operand tensors
    gemm_mma<0, Nqkv><<<dim3(Nqkv/BN, Mtot/BM), 256>>>(x, b_qkv, nullptr);

    // 2) MMA flash attention -> g_yhi/g_ylo
    attn_kernel<<<dim3(Ts/64, Bb*Hh), 128>>>();

    // 3) Output projection (MMA) -> out
    gemm_mma<1, Cc><<<dim3(Cc/BN, Mtot/BM), 256>>>(nullptr, b_out, out);
}

// round 13
// speedup vs baseline: 6.9915x; 1.1069x over previous
#include <cuda_runtime.h>
#include <cuda_bf16.h>
#include <cstdint>
#include <math.h>

// Problem constants
#define Bb 4
#define Ts 2048
#define Cc 1024
#define Hh 16
#define Dd 64
#define Mtot (Bb*Ts)        // 8192
#define Nqkv (3*Cc)         // 3072
#define Kdim Cc             // 1024

// ---------------------------------------------------------------------------
// Scratch (__device__ globals). RULE: referenced ONLY from device code.
// ---------------------------------------------------------------------------
__device__ __align__(128) __nv_bfloat16 g_xhi[Mtot*Kdim];
__device__ __align__(128) __nv_bfloat16 g_xlo[Mtot*Kdim];
__device__ __align__(128) __nv_bfloat16 g_qhi[Bb*Hh*Ts*Dd];  // [b,h,t,d], pre-scaled 1/8
__device__ __align__(128) __nv_bfloat16 g_qlo[Bb*Hh*Ts*Dd];
__device__ __align__(128) __nv_bfloat16 g_khi[Bb*Hh*Ts*Dd];  // [b,h,t,d]
__device__ __align__(128) __nv_bfloat16 g_klo[Bb*Hh*Ts*Dd];
__device__ __align__(128) __nv_bfloat16 g_vthi[Bb*Hh*Dd*Ts]; // [b,h,d,t] (transposed)
__device__ __align__(128) __nv_bfloat16 g_vtlo[Bb*Hh*Dd*Ts];
__device__ __align__(128) __nv_bfloat16 g_yhi[Mtot*Kdim];
__device__ __align__(128) __nv_bfloat16 g_ylo[Mtot*Kdim];
__device__ __align__(128) __nv_bfloat16 g_wqhi[Nqkv*Kdim];   // [N][K]
__device__ __align__(128) __nv_bfloat16 g_wqlo[Nqkv*Kdim];
__device__ __align__(128) __nv_bfloat16 g_wohi[Cc*Kdim];
__device__ __align__(128) __nv_bfloat16 g_wolo[Cc*Kdim];

// ---------------------------------------------------------------------------
// Helpers
// ---------------------------------------------------------------------------
#define MMA_BF16(c, a, b) asm volatile( \
    "mma.sync.aligned.m16n8k16.row.col.f32.bf16.bf16.f32 " \
    "{%0,%1,%2,%3}, {%4,%5,%6,%7}, {%8,%9}, {%0,%1,%2,%3};" \
    : "+f"((c)[0]), "+f"((c)[1]), "+f"((c)[2]), "+f"((c)[3]) \
    : "r"((a)[0]), "r"((a)[1]), "r"((a)[2]), "r"((a)[3]), \
      "r"((b)[0]), "r"((b)[1]))

#define CP16(s, g) \
    asm volatile("cp.async.cg.shared.global [%0], [%1], 16;" :: "r"(s), "l"(g))
#define CP_COMMIT() asm volatile("cp.async.commit_group;")
#define CP_WAIT1()  asm volatile("cp.async.wait_group 1;")
#define CP_WAIT0()  asm volatile("cp.async.wait_group 0;")

__device__ __forceinline__ uint32_t smem_to_u32(const void* p) {
    uint32_t a;
    asm("{ .reg .u64 t; cvta.to.shared.u64 t, %1; cvt.u32.u64 %0, t; }"
        : "=r"(a) : "l"(p));
    return a;
}
__device__ __forceinline__ void split2(float a, __nv_bfloat16& h, __nv_bfloat16& l) {
    __nv_bfloat16 hh = __float2bfloat16(a);
    l = __float2bfloat16(a - __bfloat162float(hh));
    h = hh;
}
__device__ __forceinline__ uint32_t pack2(__nv_bfloat16 a, __nv_bfloat16 b) {
    __nv_bfloat162 p = __halves2bfloat162(a, b);
    return *(uint32_t*)&p;
}

// ---------------------------------------------------------------------------
// x pre-split: fp32 -> g_xhi/g_xlo (float4 per thread)
// ---------------------------------------------------------------------------
__global__ void split_x_kernel(const float* __restrict__ in)
{
    const int i = blockIdx.x * blockDim.x + threadIdx.x;   // float4 index
    float4 v = *(const float4*)&in[(size_t)i * 4];
    __nv_bfloat16 h0,l0,h1,l1,h2,l2,h3,l3;
    split2(v.x, h0, l0); split2(v.y, h1, l1);
    split2(v.z, h2, l2); split2(v.w, h3, l3);
    uint2 hh = make_uint2(pack2(h0, h1), pack2(h2, h3));
    uint2 ll = make_uint2(pack2(l0, l1), pack2(l2, l3));
    *(uint2*)&g_xhi[(size_t)i * 4] = hh;
    *(uint2*)&g_xlo[(size_t)i * 4] = ll;
}

// ---------------------------------------------------------------------------
// Weight transpose + split (proven)
// ---------------------------------------------------------------------------
template<int MODE, int N>
__global__ void transpose_split_kernel(const float* __restrict__ in)
{
    __nv_bfloat16* __restrict__ hi = (MODE == 0) ? g_wqhi : g_wohi;
    __nv_bfloat16* __restrict__ lo = (MODE == 0) ? g_wqlo : g_wolo;

    __shared__ float t[32][33];
    const int n0 = blockIdx.x * 32, k0 = blockIdx.y * 32;
    #pragma unroll
    for (int i = 0; i < 4; i++) {
        int k = k0 + threadIdx.y + i * 8;
        t[threadIdx.y + i * 8][threadIdx.x] = in[(size_t)k * N + n0 + threadIdx.x];
    }
    __syncthreads();
    #pragma unroll
    for (int i = 0; i < 4; i++) {
        int n = n0 + threadIdx.y + i * 8;
        int k = k0 + threadIdx.x;
        __nv_bfloat16 h, l;
        split2(t[threadIdx.x][threadIdx.y + i * 8], h, l);
        hi[(size_t)n * Kdim + k] = h;
        lo[(size_t)n * Kdim + k] = l;
    }
}

#define BM 128
#define BN 128
#define BK 32
#define KPAD 40
#define TILE_E (BM * KPAD)         // 5120 bf16 per array tile
#define TILE_B (TILE_E * 2)        // 10240 bytes
#define STAGE_E (4 * TILE_E)       // Ahi, Alo, Bhi, Blo
#define STAGE_B (4 * TILE_B)       // 40960 bytes
#define GEMM_SMEM (2 * STAGE_B)    // 81920 bytes (dynamic)

// ---------------------------------------------------------------------------
// 3xBF16 warp-MMA GEMM, cp.async 2-stage double buffer (compute core proven).
// MODE 0: A = g_x*, B = g_wq*; epilogue splits+scatters q/k/v (round-11).
// MODE 1: A = g_y*, B = g_wo*; epilogue -> outp fp32.
// ---------------------------------------------------------------------------
template<int MODE, int N>
__global__ __launch_bounds__(256)
void gemm_mma(const float* __restrict__ bias,
              float* __restrict__ outp)
{
    const __nv_bfloat16* __restrict__ Ahi = (MODE == 0) ? g_xhi : g_yhi;
    const __nv_bfloat16* __restrict__ Alo = (MODE == 0) ? g_xlo : g_ylo;
    const __nv_bfloat16* __restrict__ Bhi = (MODE == 0) ? g_wqhi : g_wohi;
    const __nv_bfloat16* __restrict__ Blo = (MODE == 0) ? g_wqlo : g_wolo;

    extern __shared__ __align__(16) char smem_raw[];
    __nv_bfloat16* smem = (__nv_bfloat16*)smem_raw;
    const uint32_t sbase = smem_to_u32(smem_raw);

    const int tid = threadIdx.x;
    const int l = tid & 31;
    const int wid = tid >> 5;
    const int wm = wid & 3;
    const int wn = wid >> 2;
    const int m0 = blockIdx.y * BM;
    const int n0 = blockIdx.x * BN;
    const int qr = l >> 2;
    const int qc = l & 3;

    float acc[2][8][4];
    #pragma unroll
    for (int i = 0; i < 2; i++)
        #pragma unroll
        for (int j = 0; j < 8; j++)
            #pragma unroll
            for (int q = 0; q < 4; q++) acc[i][j][q] = 0.f;

    const int fr = tid >> 2;           // 0..63
    const int fs = (tid & 3) * 8;      // bf16 offset 0,8,16,24

    // ---- cp.async fill of one stage for k-chunk kc ----
    auto issue = [&](int stage, int kc) {
        const int k0 = kc * BK;
        const uint32_t s0 = sbase + (uint32_t)stage * STAGE_B;
        #pragma unroll
        for (int hx = 0; hx < 2; hx++) {
            const int r = fr + hx * 64;
            const uint32_t so = (uint32_t)(r * KPAD + fs) * 2;
            const size_t ga = (size_t)(m0 + r) * Kdim + k0 + fs;
            const size_t gb = (size_t)(n0 + r) * Kdim + k0 + fs;
            CP16(s0 + 0u*TILE_B + so, Ahi + ga);
            CP16(s0 + 1u*TILE_B + so, Alo + ga);
            CP16(s0 + 2u*TILE_B + so, Bhi + gb);
            CP16(s0 + 3u*TILE_B + so, Blo + gb);
        }
        CP_COMMIT();
    };

    const int NC = Kdim / BK;          // 32
    issue(0, 0);

    for (int kc = 0; kc < NC; kc++) {
        if (kc + 1 < NC) { issue((kc + 1) & 1, kc + 1); CP_WAIT1(); }
        else             { CP_WAIT0(); }
        __syncthreads();

        const __nv_bfloat16* sA0 = smem + (kc & 1) * STAGE_E;
        const __nv_bfloat16* sA1 = sA0 + TILE_E;
        const __nv_bfloat16* sB0 = sA0 + 2 * TILE_E;
        const __nv_bfloat16* sB1 = sA0 + 3 * TILE_E;

        #pragma unroll
        for (int kk = 0; kk < 2; kk++) {
            const int kb = kk * 16 + qc * 2;
            uint32_t bh[8][2], bl[8][2];
            #pragma unroll
            for (int nb = 0; nb < 8; nb++) {
                const int nrow = wn * 64 + nb * 8 + qr;
                bh[nb][0] = *(const uint32_t*)&sB0[nrow * KPAD + kb];
                bh[nb][1] = *(const uint32_t*)&sB0[nrow * KPAD + kb + 8];
                bl[nb][0] = *(const uint32_t*)&sB1[nrow * KPAD + kb];
                bl[nb][1] = *(const uint32_t*)&sB1[nrow * KPAD + kb + 8];
            }
            #pragma unroll
            for (int mb = 0; mb < 2; mb++) {
                const int arow = wm * 32 + mb * 16 + qr;
                uint32_t ah[4], al[4];
                ah[0] = *(const uint32_t*)&sA0[arow * KPAD + kb];
                ah[1] = *(const uint32_t*)&sA0[(arow + 8) * KPAD + kb];
                ah[2] = *(const uint32_t*)&sA0[arow * KPAD + kb + 8];
                ah[3] = *(const uint32_t*)&sA0[(arow + 8) * KPAD + kb + 8];
                al[0] = *(const uint32_t*)&sA1[arow * KPAD + kb];
                al[1] = *(const uint32_t*)&sA1[(arow + 8) * KPAD + kb];
                al[2] = *(const uint32_t*)&sA1[arow * KPAD + kb + 8];
                al[3] = *(const uint32_t*)&sA1[(arow + 8) * KPAD + kb + 8];
                #pragma unroll
                for (int nb = 0; nb < 8; nb++) {
                    MMA_BF16(acc[mb][nb], ah, bh[nb]);
                    MMA_BF16(acc[mb][nb], ah, bl[nb]);
                    MMA_BF16(acc[mb][nb], al, bh[nb]);
                }
            }
        }
        __syncthreads();   // all warps done with this stage before re-fill
    }

    // ---- epilogue (round-11 proven) ----
    #pragma unroll
    for (int mb = 0; mb < 2; mb++) {
        #pragma unroll
        for (int nb = 0; nb < 8; nb++) {
            const int col = wn * 64 + nb * 8 + qc * 2;
            const int n = n0 + col;
            const float bv0 = bias[n];
            const float bv1 = bias[n + 1];
            #pragma unroll
            for (int half = 0; half < 2; half++) {
                const int m = m0 + wm * 32 + mb * 16 + qr + half * 8;
                float v0 = acc[mb][nb][half*2+0] + bv0;
                float v1 = acc[mb][nb][half*2+1] + bv1;
                if (MODE == 0) {
                    const int b = m >> 11, t = m & (Ts - 1);
                    const int which = n >> 10;
                    const int cn = n & (Cc - 1);
                    const int h = cn >> 6, d = cn & 63;
                    const size_t bh_ = (size_t)(b * Hh + h);
                    __nv_bfloat16 h0, l0, h1, l1;
                    if (which == 0) {
                        split2(v0 * 0.125f, h0, l0);
                        split2(v1 * 0.125f, h1, l1);
                        const size_t idx = (bh_ * Ts + t) * Dd + d;
                        *(uint32_t*)&g_qhi[idx] = pack2(h0, h1);
                        *(uint32_t*)&g_qlo[idx] = pack2(l0, l1);
                    } else if (which == 1) {
                        split2(v0, h0, l0);
                        split2(v1, h1, l1);
                        const size_t idx = (bh_ * Ts + t) * Dd + d;
                        *(uint32_t*)&g_khi[idx] = pack2(h0, h1);
                        *(uint32_t*)&g_klo[idx] = pack2(l0, l1);
                    } else {
                        split2(v0, h0, l0);
                        split2(v1, h1, l1);
                        const size_t i0 = (bh_ * Dd + d) * Ts + t;
                        const size_t i1 = (bh_ * Dd + d + 1) * Ts + t;
                        g_vthi[i0] = h0; g_vtlo[i0] = l0;
                        g_vthi[i1] = h1; g_vtlo[i1] = l1;
                    }
                } else {
                    outp[(size_t)m * N + n]     = v0;
                    outp[(size_t)m * N + n + 1] = v1;
                }
            }
        }
    }
}

// ---------------------------------------------------------------------------
// MMA flash attention (round-11 proven, unchanged)
// ---------------------------------------------------------------------------
#define SPAD 72

__global__ __launch_bounds__(128)
void attn_kernel()
{
    __shared__ __align__(16) __nv_bfloat16 sKh[64 * SPAD];
    __shared__ __align__(16) __nv_bfloat16 sKl[64 * SPAD];
    __shared__ __align__(16) __nv_bfloat16 sVh[64 * SPAD];
    __shared__ __align__(16) __nv_bfloat16 sVl[64 * SPAD];

    const int tid = threadIdx.x;
    const int l = tid & 31;
    const int wm = tid >> 5;
    const int qr = l >> 2;
    const int qc = l & 3;
    const int qt = blockIdx.x;
    const int bh = blockIdx.y;

    const size_t qk_base = (size_t)bh * Ts * Dd;
    const size_t vt_base = (size_t)bh * Dd * Ts;

    uint32_t qh[4][4], ql[4][4];
    {
        const int r0 = qt * 64 + wm * 16 + qr;
        #pragma unroll
        for (int ks = 0; ks < 4; ks++) {
            const int kcol = ks * 16 + qc * 2;
            qh[ks][0] = *(const uint32_t*)&g_qhi[qk_base + (size_t)r0 * Dd + kcol];
            qh[ks][1] = *(const uint32_t*)&g_qhi[qk_base + (size_t)(r0 + 8) * Dd + kcol];
            qh[ks][2] = *(const uint32_t*)&g_qhi[qk_base + (size_t)r0 * Dd + kcol + 8];
            qh[ks][3] = *(const uint32_t*)&g_qhi[qk_base + (size_t)(r0 + 8) * Dd + kcol + 8];
            ql[ks][0] = *(const uint32_t*)&g_qlo[qk_base + (size_t)r0 * Dd + kcol];
            ql[ks][1] = *(const uint32_t*)&g_qlo[qk_base + (size_t)(r0 + 8) * Dd + kcol];
            ql[ks][2] = *(const uint32_t*)&g_qlo[qk_base + (size_t)r0 * Dd + kcol + 8];
            ql[ks][3] = *(const uint32_t*)&g_qlo[qk_base + (size_t)(r0 + 8) * Dd + kcol + 8];
        }
    }

    float o[8][4];
    #pragma unroll
    for (int i = 0; i < 8; i++)
        #pragma unroll
        for (int j = 0; j < 4; j++) o[i][j] = 0.f;
    float m0v = -1e30f, m1v = -1e30f, l0v = 0.f, l1v = 0.f;

    for (int kt = 0; kt <= qt; kt++) {
        __syncthreads();
        for (int i = tid; i < 512; i += 128) {
            const int row = i >> 3;
            const int seg = (i & 7) * 8;
            const size_t gk = qk_base + (size_t)(kt * 64 + row) * Dd + seg;
            *(uint4*)&sKh[row * SPAD + seg] = *(const uint4*)&g_khi[gk];
            *(uint4*)&sKl[row * SPAD + seg] = *(const uint4*)&g_klo[gk];
            const size_t gv = vt_base + (size_t)row * Ts + kt * 64 + seg;
            *(uint4*)&sVh[row * SPAD + seg] = *(const uint4*)&g_vthi[gv];
            *(uint4*)&sVl[row * SPAD + seg] = *(const uint4*)&g_vtlo[gv];
        }
        __syncthreads();

        float c[8][4];
        #pragma unroll
        for (int nb = 0; nb < 8; nb++)
            #pragma unroll
            for (int q = 0; q < 4; q++) c[nb][q] = 0.f;

        #pragma unroll
        for (int ks = 0; ks < 4; ks++) {
            const int kb = ks * 16 + qc * 2;
            #pragma unroll
            for (int nb = 0; nb < 8; nb++) {
                const int nrow = nb * 8 + qr;
                uint32_t bhf[2], blf[2];
                bhf[0] = *(const uint32_t*)&sKh[nrow * SPAD + kb];
                bhf[1] = *(const uint32_t*)&sKh[nrow * SPAD + kb + 8];
                blf[0] = *(const uint32_t*)&sKl[nrow * SPAD + kb];
                blf[1] = *(const uint32_t*)&sKl[nrow * SPAD + kb + 8];
                MMA_BF16(c[nb], qh[ks], bhf);
                MMA_BF16(c[nb], qh[ks], blf);
                MMA_BF16(c[nb], ql[ks], bhf);
            }
        }

        if (kt == qt) {
            const int r0 = qt * 64 + wm * 16 + qr;
            #pragma unroll
            for (int nb = 0; nb < 8; nb++) {
                const int col = kt * 64 + nb * 8 + qc * 2;
                if (col > r0)     c[nb][0] = -1e30f;
                if (col + 1 > r0) c[nb][1] = -1e30f;
                if (col > r0 + 8)     c[nb][2] = -1e30f;
                if (col + 1 > r0 + 8) c[nb][3] = -1e30f;
            }
        }

        float rmax0 = -1e30f, rmax1 = -1e30f;
        #pragma unroll
        for (int nb = 0; nb < 8; nb++) {
            rmax0 = fmaxf(rmax0, fmaxf(c[nb][0], c[nb][1]));
            rmax1 = fmaxf(rmax1, fmaxf(c[nb][2], c[nb][3]));
        }
        #pragma unroll
        for (int off = 1; off <= 2; off <<= 1) {
            rmax0 = fmaxf(rmax0, __shfl_xor_sync(0xffffffffu, rmax0, off));
            rmax1 = fmaxf(rmax1, __shfl_xor_sync(0xffffffffu, rmax1, off));
        }
        const float mn0 = fmaxf(m0v, rmax0);
        const float mn1 = fmaxf(m1v, rmax1);
        const float cf0 = __expf(m0v - mn0);
        const float cf1 = __expf(m1v - mn1);
        m0v = mn0; m1v = mn1;

        float s0 = 0.f, s1 = 0.f;
        #pragma unroll
        for (int nb = 0; nb < 8; nb++) {
            c[nb][0] = __expf(c[nb][0] - mn0); s0 += c[nb][0];
            c[nb][1] = __expf(c[nb][1] - mn0); s0 += c[nb][1];
            c[nb][2] = __expf(c[nb][2] - mn1); s1 += c[nb][2];
            c[nb][3] = __expf(c[nb][3] - mn1); s1 += c[nb][3];
        }
        #pragma unroll
        for (int off = 1; off <= 2; off <<= 1) {
            s0 += __shfl_xor_sync(0xffffffffu, s0, off);
            s1 += __shfl_xor_sync(0xffffffffu, s1, off);
        }
        l0v = l0v * cf0 + s0;
        l1v = l1v * cf1 + s1;
        #pragma unroll
        for (int i = 0; i < 8; i++) {
            o[i][0] *= cf0; o[i][1] *= cf0;
            o[i][2] *= cf1; o[i][3] *= cf1;
        }

        uint32_t ph[4][4], pl[4][4];
        #pragma unroll
        for (int ks2 = 0; ks2 < 4; ks2++) {
            #pragma unroll
            for (int part = 0; part < 4; part++) {
                const int nb = 2 * ks2 + (part >> 1);
                const int base = (part & 1) * 2;
                const int aidx = (part >> 1) * 2 + (part & 1);
                const float v0 = c[nb][base + 0];
                const float v1 = c[nb][base + 1];
                __nv_bfloat16 h0, lo0, h1, lo1;
                split2(v0, h0, lo0);
                split2(v1, h1, lo1);
                ph[ks2][aidx] = pack2(h0, h1);
                pl[ks2][aidx] = pack2(lo0, lo1);
            }
        }

        #pragma unroll
        for (int ks2 = 0; ks2 < 4; ks2++) {
            const int kb = ks2 * 16 + qc * 2;
            #pragma unroll
            for (int nb2 = 0; nb2 < 8; nb2++) {
                const int nrow = nb2 * 8 + qr;
                uint32_t vhf[2], vlf[2];
                vhf[0] = *(const uint32_t*)&sVh[nrow * SPAD + kb];
                vhf[1] = *(const uint32_t*)&sVh[nrow * SPAD + kb + 8];
                vlf[0] = *(const uint32_t*)&sVl[nrow * SPAD + kb];
                vlf[1] = *(const uint32_t*)&sVl[nrow * SPAD + kb + 8];
                MMA_BF16(o[nb2], ph[ks2], vhf);
                MMA_BF16(o[nb2], ph[ks2], vlf);
                MMA_BF16(o[nb2], pl[ks2], vhf);
            }
        }
    }

    const int b = bh >> 4, h = bh & 15;
    const float inv0 = 1.0f / l0v;
    const float inv1 = 1.0f / l1v;
    const int t0 = qt * 64 + wm * 16 + qr;
    #pragma unroll
    for (int nb2 = 0; nb2 < 8; nb2++) {
        const int d = nb2 * 8 + qc * 2;
        {
            const size_t idx = (size_t)(b * Ts + t0) * Cc + h * Dd + d;
            __nv_bfloat16 h0, lo0, h1, lo1;
            split2(o[nb2][0] * inv0, h0, lo0);
            split2(o[nb2][1] * inv0, h1, lo1);
            *(uint32_t*)&g_yhi[idx] = pack2(h0, h1);
            *(uint32_t*)&g_ylo[idx] = pack2(lo0, lo1);
        }
        {
            const size_t idx = (size_t)(b * Ts + t0 + 8) * Cc + h * Dd + d;
            __nv_bfloat16 h0, lo0, h1, lo1;
            split2(o[nb2][2] * inv1, h0, lo0);
            split2(o[nb2][3] * inv1, h1, lo1);
            *(uint32_t*)&g_yhi[idx] = pack2(h0, h1);
            *(uint32_t*)&g_ylo[idx] = pack2(lo0, lo1);
        }
    }
}

// ---------------------------------------------------------------------------
extern "C" void kernel_launch(void* const* d_in, const int* in_sizes, int n_in,
                              void* d_out, int out_size)
{
    (void)in_sizes; (void)n_in; (void)out_size;
    const float* x     = (const float*)d_in[0];
    const float* w_qkv = (const float*)d_in[1];
    const float* b_qkv = (const float*)d_in[2];
    const float* w_out = (const float*)d_in[3];
    const float* b_out = (const float*)d_in[4];
    float* out = (float*)d_out;

    cudaFuncSetAttribute(gemm_mma<0, Nqkv>,
                         cudaFuncAttributeMaxDynamicSharedMemorySize, GEMM_SMEM);
    cudaFuncSetAttribute(gemm_mma<1, Cc>,
                         cudaFuncAttributeMaxDynamicSharedMemorySize, GEMM_SMEM);

    // 0) Pre-split x and weights into bf16 hi/lo device globals
    split_x_kernel<<<(Mtot*Kdim)/(256*4), 256>>>(x);
    transpose_split_kernel<0, Nqkv><<<dim3(Nqkv/32, Kdim/32), dim3(32,8)>>>(w_qkv);
    transpose_split_kernel<1, Cc><<<dim3(Cc/32, Kdim/32), dim3(32,8)>>>(w_out);

    // 1) QKV projection (MMA, cp.async pipelined) -> q/k/v^T operand tensors
    gemm_mma<0, Nqkv><<<dim3(Nqkv/BN, Mtot/BM), 256, GEMM_SMEM>>>(b_qkv, nullptr);

    // 2) MMA flash attention -> g_yhi/g_ylo
    attn_kernel<<<dim3(Ts/64, Bb*Hh), 128>>>();

    // 3) Output projection (MMA, cp.async pipelined) -> out
    gemm_mma<1, Cc><<<dim3(Cc/BN, Mtot/BM), 256, GEMM_SMEM>>>(b_out, out);
}

// round 14
// speedup vs baseline: 7.7837x; 1.1133x over previous
#include <cuda_runtime.h>
#include <cuda_bf16.h>
#include <cstdint>
#include <math.h>

// Problem constants
#define Bb 4
#define Ts 2048
#define Cc 1024
#define Hh 16
#define Dd 64
#define Mtot (Bb*Ts)        // 8192
#define Nqkv (3*Cc)         // 3072
#define Kdim Cc             // 1024

// ---------------------------------------------------------------------------
// Scratch (__device__ globals). RULE: referenced ONLY from device code.
// ---------------------------------------------------------------------------
__device__ __align__(128) __nv_bfloat16 g_xhi[Mtot*Kdim];
__device__ __align__(128) __nv_bfloat16 g_xlo[Mtot*Kdim];
__device__ __align__(128) __nv_bfloat16 g_qhi[Bb*Hh*Ts*Dd];  // [b,h,t,d], pre-scaled 1/8
__device__ __align__(128) __nv_bfloat16 g_qlo[Bb*Hh*Ts*Dd];
__device__ __align__(128) __nv_bfloat16 g_khi[Bb*Hh*Ts*Dd];  // [b,h,t,d]
__device__ __align__(128) __nv_bfloat16 g_klo[Bb*Hh*Ts*Dd];
__device__ __align__(128) __nv_bfloat16 g_vthi[Bb*Hh*Dd*Ts]; // [b,h,d,t] (transposed)
__device__ __align__(128) __nv_bfloat16 g_vtlo[Bb*Hh*Dd*Ts];
__device__ __align__(128) __nv_bfloat16 g_yhi[Mtot*Kdim];
__device__ __align__(128) __nv_bfloat16 g_ylo[Mtot*Kdim];
__device__ __align__(128) __nv_bfloat16 g_wqhi[Nqkv*Kdim];   // [N][K]
__device__ __align__(128) __nv_bfloat16 g_wqlo[Nqkv*Kdim];
__device__ __align__(128) __nv_bfloat16 g_wohi[Cc*Kdim];
__device__ __align__(128) __nv_bfloat16 g_wolo[Cc*Kdim];

// ---------------------------------------------------------------------------
// Helpers
// ---------------------------------------------------------------------------
#define MMA_BF16(c, a, b) asm volatile( \
    "mma.sync.aligned.m16n8k16.row.col.f32.bf16.bf16.f32 " \
    "{%0,%1,%2,%3}, {%4,%5,%6,%7}, {%8,%9}, {%0,%1,%2,%3};" \
    : "+f"((c)[0]), "+f"((c)[1]), "+f"((c)[2]), "+f"((c)[3]) \
    : "r"((a)[0]), "r"((a)[1]), "r"((a)[2]), "r"((a)[3]), \
      "r"((b)[0]), "r"((b)[1]))

#define CP16(s, g) \
    asm volatile("cp.async.cg.shared.global [%0], [%1], 16;" :: "r"(s), "l"(g))
#define CP_COMMIT() asm volatile("cp.async.commit_group;")
#define CP_WAIT1()  asm volatile("cp.async.wait_group 1;")
#define CP_WAIT0()  asm volatile("cp.async.wait_group 0;")

__device__ __forceinline__ uint32_t smem_to_u32(const void* p) {
    uint32_t a;
    asm("{ .reg .u64 t; cvta.to.shared.u64 t, %1; cvt.u32.u64 %0, t; }"
        : "=r"(a) : "l"(p));
    return a;
}
__device__ __forceinline__ void split2(float a, __nv_bfloat16& h, __nv_bfloat16& l) {
    __nv_bfloat16 hh = __float2bfloat16(a);
    l = __float2bfloat16(a - __bfloat162float(hh));
    h = hh;
}
__device__ __forceinline__ uint32_t pack2(__nv_bfloat16 a, __nv_bfloat16 b) {
    __nv_bfloat162 p = __halves2bfloat162(a, b);
    return *(uint32_t*)&p;
}

// ---------------------------------------------------------------------------
// x pre-split: fp32 -> g_xhi/g_xlo
// ---------------------------------------------------------------------------
__global__ void split_x_kernel(const float* __restrict__ in)
{
    const int i = blockIdx.x * blockDim.x + threadIdx.x;
    float4 v = *(const float4*)&in[(size_t)i * 4];
    __nv_bfloat16 h0,l0,h1,l1,h2,l2,h3,l3;
    split2(v.x, h0, l0); split2(v.y, h1, l1);
    split2(v.z, h2, l2); split2(v.w, h3, l3);
    uint2 hh = make_uint2(pack2(h0, h1), pack2(h2, h3));
    uint2 ll = make_uint2(pack2(l0, l1), pack2(l2, l3));
    *(uint2*)&g_xhi[(size_t)i * 4] = hh;
    *(uint2*)&g_xlo[(size_t)i * 4] = ll;
}

// ---------------------------------------------------------------------------
// Weight transpose + split (proven)
// ---------------------------------------------------------------------------
template<int MODE, int N>
__global__ void transpose_split_kernel(const float* __restrict__ in)
{
    __nv_bfloat16* __restrict__ hi = (MODE == 0) ? g_wqhi : g_wohi;
    __nv_bfloat16* __restrict__ lo = (MODE == 0) ? g_wqlo : g_wolo;

    __shared__ float t[32][33];
    const int n0 = blockIdx.x * 32, k0 = blockIdx.y * 32;
    #pragma unroll
    for (int i = 0; i < 4; i++) {
        int k = k0 + threadIdx.y + i * 8;
        t[threadIdx.y + i * 8][threadIdx.x] = in[(size_t)k * N + n0 + threadIdx.x];
    }
    __syncthreads();
    #pragma unroll
    for (int i = 0; i < 4; i++) {
        int n = n0 + threadIdx.y + i * 8;
        int k = k0 + threadIdx.x;
        __nv_bfloat16 h, l;
        split2(t[threadIdx.x][threadIdx.y + i * 8], h, l);
        hi[(size_t)n * Kdim + k] = h;
        lo[(size_t)n * Kdim + k] = l;
    }
}

#define BM 128
#define BN 128
#define BK 32
#define KPAD 40
#define TILE_E (BM * KPAD)
#define TILE_B (TILE_E * 2)
#define STAGE_E (4 * TILE_E)
#define STAGE_B (4 * TILE_B)
#define GEMM_SMEM (2 * STAGE_B)    // 81920 bytes

// ---------------------------------------------------------------------------
// 3xBF16 warp-MMA GEMM, cp.async pipelined, product-major MMA order.
// ---------------------------------------------------------------------------
template<int MODE, int N>
__global__ __launch_bounds__(256)
void gemm_mma(const float* __restrict__ bias,
              float* __restrict__ outp)
{
    const __nv_bfloat16* __restrict__ Ahi = (MODE == 0) ? g_xhi : g_yhi;
    const __nv_bfloat16* __restrict__ Alo = (MODE == 0) ? g_xlo : g_ylo;
    const __nv_bfloat16* __restrict__ Bhi = (MODE == 0) ? g_wqhi : g_wohi;
    const __nv_bfloat16* __restrict__ Blo = (MODE == 0) ? g_wqlo : g_wolo;

    extern __shared__ __align__(16) char smem_raw[];
    __nv_bfloat16* smem = (__nv_bfloat16*)smem_raw;
    const uint32_t sbase = smem_to_u32(smem_raw);

    const int tid = threadIdx.x;
    const int l = tid & 31;
    const int wid = tid >> 5;
    const int wm = wid & 3;
    const int wn = wid >> 2;
    const int m0 = blockIdx.y * BM;
    const int n0 = blockIdx.x * BN;
    const int qr = l >> 2;
    const int qc = l & 3;

    float acc[2][8][4];
    #pragma unroll
    for (int i = 0; i < 2; i++)
        #pragma unroll
        for (int j = 0; j < 8; j++)
            #pragma unroll
            for (int q = 0; q < 4; q++) acc[i][j][q] = 0.f;

    const int fr = tid >> 2;
    const int fs = (tid & 3) * 8;

    auto issue = [&](int stage, int kc) {
        const int k0 = kc * BK;
        const uint32_t s0 = sbase + (uint32_t)stage * STAGE_B;
        #pragma unroll
        for (int hx = 0; hx < 2; hx++) {
            const int r = fr + hx * 64;
            const uint32_t so = (uint32_t)(r * KPAD + fs) * 2;
            const size_t ga = (size_t)(m0 + r) * Kdim + k0 + fs;
            const size_t gb = (size_t)(n0 + r) * Kdim + k0 + fs;
            CP16(s0 + 0u*TILE_B + so, Ahi + ga);
            CP16(s0 + 1u*TILE_B + so, Alo + ga);
            CP16(s0 + 2u*TILE_B + so, Bhi + gb);
            CP16(s0 + 3u*TILE_B + so, Blo + gb);
        }
        CP_COMMIT();
    };

    const int NC = Kdim / BK;
    issue(0, 0);

    for (int kc = 0; kc < NC; kc++) {
        if (kc + 1 < NC) { issue((kc + 1) & 1, kc + 1); CP_WAIT1(); }
        else             { CP_WAIT0(); }
        __syncthreads();

        const __nv_bfloat16* sA0 = smem + (kc & 1) * STAGE_E;
        const __nv_bfloat16* sA1 = sA0 + TILE_E;
        const __nv_bfloat16* sB0 = sA0 + 2 * TILE_E;
        const __nv_bfloat16* sB1 = sA0 + 3 * TILE_E;

        #pragma unroll
        for (int kk = 0; kk < 2; kk++) {
            const int kb = kk * 16 + qc * 2;
            uint32_t bh[8][2], bl[8][2];
            #pragma unroll
            for (int nb = 0; nb < 8; nb++) {
                const int nrow = wn * 64 + nb * 8 + qr;
                bh[nb][0] = *(const uint32_t*)&sB0[nrow * KPAD + kb];
                bh[nb][1] = *(const uint32_t*)&sB0[nrow * KPAD + kb + 8];
                bl[nb][0] = *(const uint32_t*)&sB1[nrow * KPAD + kb];
                bl[nb][1] = *(const uint32_t*)&sB1[nrow * KPAD + kb + 8];
            }
            uint32_t ah[2][4], al[2][4];
            #pragma unroll
            for (int mb = 0; mb < 2; mb++) {
                const int arow = wm * 32 + mb * 16 + qr;
                ah[mb][0] = *(const uint32_t*)&sA0[arow * KPAD + kb];
                ah[mb][1] = *(const uint32_t*)&sA0[(arow + 8) * KPAD + kb];
                ah[mb][2] = *(const uint32_t*)&sA0[arow * KPAD + kb + 8];
                ah[mb][3] = *(const uint32_t*)&sA0[(arow + 8) * KPAD + kb + 8];
                al[mb][0] = *(const uint32_t*)&sA1[arow * KPAD + kb];
                al[mb][1] = *(const uint32_t*)&sA1[(arow + 8) * KPAD + kb];
                al[mb][2] = *(const uint32_t*)&sA1[arow * KPAD + kb + 8];
                al[mb][3] = *(const uint32_t*)&sA1[(arow + 8) * KPAD + kb + 8];
            }
            // Product-major order: dependent MMAs to the same acc are 16 apart
            #pragma unroll
            for (int mb = 0; mb < 2; mb++)
                #pragma unroll
                for (int nb = 0; nb < 8; nb++)
                    MMA_BF16(acc[mb][nb], ah[mb], bh[nb]);
            #pragma unroll
            for (int mb = 0; mb < 2; mb++)
                #pragma unroll
                for (int nb = 0; nb < 8; nb++)
                    MMA_BF16(acc[mb][nb], ah[mb], bl[nb]);
            #pragma unroll
            for (int mb = 0; mb < 2; mb++)
                #pragma unroll
                for (int nb = 0; nb < 8; nb++)
                    MMA_BF16(acc[mb][nb], al[mb], bh[nb]);
        }
        __syncthreads();
    }

    // ---- epilogue (proven) ----
    #pragma unroll
    for (int mb = 0; mb < 2; mb++) {
        #pragma unroll
        for (int nb = 0; nb < 8; nb++) {
            const int col = wn * 64 + nb * 8 + qc * 2;
            const int n = n0 + col;
            const float bv0 = bias[n];
            const float bv1 = bias[n + 1];
            #pragma unroll
            for (int half = 0; half < 2; half++) {
                const int m = m0 + wm * 32 + mb * 16 + qr + half * 8;
                float v0 = acc[mb][nb][half*2+0] + bv0;
                float v1 = acc[mb][nb][half*2+1] + bv1;
                if (MODE == 0) {
                    const int b = m >> 11, t = m & (Ts - 1);
                    const int which = n >> 10;
                    const int cn = n & (Cc - 1);
                    const int h = cn >> 6, d = cn & 63;
                    const size_t bh_ = (size_t)(b * Hh + h);
                    __nv_bfloat16 h0, l0, h1, l1;
                    if (which == 0) {
                        split2(v0 * 0.125f, h0, l0);
                        split2(v1 * 0.125f, h1, l1);
                        const size_t idx = (bh_ * Ts + t) * Dd + d;
                        *(uint32_t*)&g_qhi[idx] = pack2(h0, h1);
                        *(uint32_t*)&g_qlo[idx] = pack2(l0, l1);
                    } else if (which == 1) {
                        split2(v0, h0, l0);
                        split2(v1, h1, l1);
                        const size_t idx = (bh_ * Ts + t) * Dd + d;
                        *(uint32_t*)&g_khi[idx] = pack2(h0, h1);
                        *(uint32_t*)&g_klo[idx] = pack2(l0, l1);
                    } else {
                        split2(v0, h0, l0);
                        split2(v1, h1, l1);
                        const size_t i0 = (bh_ * Dd + d) * Ts + t;
                        const size_t i1 = (bh_ * Dd + d + 1) * Ts + t;
                        g_vthi[i0] = h0; g_vtlo[i0] = l0;
                        g_vthi[i1] = h1; g_vtlo[i1] = l1;
                    }
                } else {
                    outp[(size_t)m * N + n]     = v0;
                    outp[(size_t)m * N + n + 1] = v1;
                }
            }
        }
    }
}

// ---------------------------------------------------------------------------
// MMA flash attention, cp.async double-buffered K/V tiles, product-major MMAs.
// Dynamic smem: 2 stages x (4 arrays x 64 x SPAD bf16) = 73728 B.
// ---------------------------------------------------------------------------
#define SPAD 72
#define AT_ARR_E (64 * SPAD)             // 4608 bf16 per array
#define AT_ARR_B (AT_ARR_E * 2)          // 9216 bytes
#define AT_STAGE_E (4 * AT_ARR_E)        // 18432 bf16
#define AT_STAGE_B (4 * AT_ARR_B)        // 36864 bytes
#define ATTN_SMEM (2 * AT_STAGE_B)       // 73728 bytes

__global__ __launch_bounds__(128)
void attn_kernel()
{
    extern __shared__ __align__(16) char asmem_raw[];
    __nv_bfloat16* smem = (__nv_bfloat16*)asmem_raw;
    const uint32_t sbase = smem_to_u32(asmem_raw);

    const int tid = threadIdx.x;
    const int l = tid & 31;
    const int wm = tid >> 5;
    const int qr = l >> 2;
    const int qc = l & 3;
    const int qt = blockIdx.x;
    const int bh = blockIdx.y;

    const size_t qk_base = (size_t)bh * Ts * Dd;
    const size_t vt_base = (size_t)bh * Dd * Ts;

    auto issueKV = [&](int stage, int kt) {
        const uint32_t s0 = sbase + (uint32_t)stage * AT_STAGE_B;
        #pragma unroll
        for (int rep = 0; rep < 4; rep++) {
            const int i = tid + rep * 128;
            const int row = i >> 3;
            const int seg = (i & 7) * 8;
            const uint32_t so = (uint32_t)(row * SPAD + seg) * 2;
            const size_t gk = qk_base + (size_t)(kt * 64 + row) * Dd + seg;
            const size_t gv = vt_base + (size_t)row * Ts + kt * 64 + seg;
            CP16(s0 + 0u*AT_ARR_B + so, g_khi + gk);
            CP16(s0 + 1u*AT_ARR_B + so, g_klo + gk);
            CP16(s0 + 2u*AT_ARR_B + so, g_vthi + gv);
            CP16(s0 + 3u*AT_ARR_B + so, g_vtlo + gv);
        }
        CP_COMMIT();
    };

    // Q fragments (registers, loaded once)
    uint32_t qh[4][4], ql[4][4];
    {
        const int r0 = qt * 64 + wm * 16 + qr;
        #pragma unroll
        for (int ks = 0; ks < 4; ks++) {
            const int kcol = ks * 16 + qc * 2;
            qh[ks][0] = *(const uint32_t*)&g_qhi[qk_base + (size_t)r0 * Dd + kcol];
            qh[ks][1] = *(const uint32_t*)&g_qhi[qk_base + (size_t)(r0 + 8) * Dd + kcol];
            qh[ks][2] = *(const uint32_t*)&g_qhi[qk_base + (size_t)r0 * Dd + kcol + 8];
            qh[ks][3] = *(const uint32_t*)&g_qhi[qk_base + (size_t)(r0 + 8) * Dd + kcol + 8];
            ql[ks][0] = *(const uint32_t*)&g_qlo[qk_base + (size_t)r0 * Dd + kcol];
            ql[ks][1] = *(const uint32_t*)&g_qlo[qk_base + (size_t)(r0 + 8) * Dd + kcol];
            ql[ks][2] = *(const uint32_t*)&g_qlo[qk_base + (size_t)r0 * Dd + kcol + 8];
            ql[ks][3] = *(const uint32_t*)&g_qlo[qk_base + (size_t)(r0 + 8) * Dd + kcol + 8];
        }
    }

    float o[8][4];
    #pragma unroll
    for (int i = 0; i < 8; i++)
        #pragma unroll
        for (int j = 0; j < 4; j++) o[i][j] = 0.f;
    float m0v = -1e30f, m1v = -1e30f, l0v = 0.f, l1v = 0.f;

    issueKV(0, 0);

    for (int kt = 0; kt <= qt; kt++) {
        if (kt + 1 <= qt) { issueKV((kt + 1) & 1, kt + 1); CP_WAIT1(); }
        else              { CP_WAIT0(); }
        __syncthreads();

        const __nv_bfloat16* sKh = smem + (kt & 1) * AT_STAGE_E;
        const __nv_bfloat16* sKl = sKh + AT_ARR_E;
        const __nv_bfloat16* sVh = sKh + 2 * AT_ARR_E;
        const __nv_bfloat16* sVl = sKh + 3 * AT_ARR_E;

        // ---- S = Q K^T (product-major) ----
        float c[8][4];
        #pragma unroll
        for (int nb = 0; nb < 8; nb++)
            #pragma unroll
            for (int q = 0; q < 4; q++) c[nb][q] = 0.f;

        #pragma unroll
        for (int ks = 0; ks < 4; ks++) {
            const int kb = ks * 16 + qc * 2;
            uint32_t bhf[8][2], blf[8][2];
            #pragma unroll
            for (int nb = 0; nb < 8; nb++) {
                const int nrow = nb * 8 + qr;
                bhf[nb][0] = *(const uint32_t*)&sKh[nrow * SPAD + kb];
                bhf[nb][1] = *(const uint32_t*)&sKh[nrow * SPAD + kb + 8];
                blf[nb][0] = *(const uint32_t*)&sKl[nrow * SPAD + kb];
                blf[nb][1] = *(const uint32_t*)&sKl[nrow * SPAD + kb + 8];
            }
            #pragma unroll
            for (int nb = 0; nb < 8; nb++) MMA_BF16(c[nb], qh[ks], bhf[nb]);
            #pragma unroll
            for (int nb = 0; nb < 8; nb++) MMA_BF16(c[nb], qh[ks], blf[nb]);
            #pragma unroll
            for (int nb = 0; nb < 8; nb++) MMA_BF16(c[nb], ql[ks], bhf[nb]);
        }

        // ---- causal mask on diagonal tile ----
        if (kt == qt) {
            const int r0 = qt * 64 + wm * 16 + qr;
            #pragma unroll
            for (int nb = 0; nb < 8; nb++) {
                const int col = kt * 64 + nb * 8 + qc * 2;
                if (col > r0)     c[nb][0] = -1e30f;
                if (col + 1 > r0) c[nb][1] = -1e30f;
                if (col > r0 + 8)     c[nb][2] = -1e30f;
                if (col + 1 > r0 + 8) c[nb][3] = -1e30f;
            }
        }

        // ---- online softmax ----
        float rmax0 = -1e30f, rmax1 = -1e30f;
        #pragma unroll
        for (int nb = 0; nb < 8; nb++) {
            rmax0 = fmaxf(rmax0, fmaxf(c[nb][0], c[nb][1]));
            rmax1 = fmaxf(rmax1, fmaxf(c[nb][2], c[nb][3]));
        }
        #pragma unroll
        for (int off = 1; off <= 2; off <<= 1) {
            rmax0 = fmaxf(rmax0, __shfl_xor_sync(0xffffffffu, rmax0, off));
            rmax1 = fmaxf(rmax1, __shfl_xor_sync(0xffffffffu, rmax1, off));
        }
        const float mn0 = fmaxf(m0v, rmax0);
        const float mn1 = fmaxf(m1v, rmax1);
        const float cf0 = __expf(m0v - mn0);
        const float cf1 = __expf(m1v - mn1);
        m0v = mn0; m1v = mn1;

        float s0 = 0.f, s1 = 0.f;
        #pragma unroll
        for (int nb = 0; nb < 8; nb++) {
            c[nb][0] = __expf(c[nb][0] - mn0); s0 += c[nb][0];
            c[nb][1] = __expf(c[nb][1] - mn0); s0 += c[nb][1];
            c[nb][2] = __expf(c[nb][2] - mn1); s1 += c[nb][2];
            c[nb][3] = __expf(c[nb][3] - mn1); s1 += c[nb][3];
        }
        #pragma unroll
        for (int off = 1; off <= 2; off <<= 1) {
            s0 += __shfl_xor_sync(0xffffffffu, s0, off);
            s1 += __shfl_xor_sync(0xffffffffu, s1, off);
        }
        l0v = l0v * cf0 + s0;
        l1v = l1v * cf1 + s1;
        #pragma unroll
        for (int i = 0; i < 8; i++) {
            o[i][0] *= cf0; o[i][1] *= cf0;
            o[i][2] *= cf1; o[i][3] *= cf1;
        }

        // ---- P fragments in-register, hi/lo split ----
        uint32_t ph[4][4], pl[4][4];
        #pragma unroll
        for (int ks2 = 0; ks2 < 4; ks2++) {
            #pragma unroll
            for (int part = 0; part < 4; part++) {
                const int nb = 2 * ks2 + (part >> 1);
                const int base = (part & 1) * 2;
                const int aidx = (part >> 1) * 2 + (part & 1);
                const float v0 = c[nb][base + 0];
                const float v1 = c[nb][base + 1];
                __nv_bfloat16 h0, lo0, h1, lo1;
                split2(v0, h0, lo0);
                split2(v1, h1, lo1);
                ph[ks2][aidx] = pack2(h0, h1);
                pl[ks2][aidx] = pack2(lo0, lo1);
            }
        }

        // ---- O += P @ V (product-major) ----
        #pragma unroll
        for (int ks2 = 0; ks2 < 4; ks2++) {
            const int kb = ks2 * 16 + qc * 2;
            uint32_t vhf[8][2], vlf[8][2];
            #pragma unroll
            for (int nb2 = 0; nb2 < 8; nb2++) {
                const int nrow = nb2 * 8 + qr;
                vhf[nb2][0] = *(const uint32_t*)&sVh[nrow * SPAD + kb];
                vhf[nb2][1] = *(const uint32_t*)&sVh[nrow * SPAD + kb + 8];
                vlf[nb2][0] = *(const uint32_t*)&sVl[nrow * SPAD + kb];
                vlf[nb2][1] = *(const uint32_t*)&sVl[nrow * SPAD + kb + 8];
            }
            #pragma unroll
            for (int nb2 = 0; nb2 < 8; nb2++) MMA_BF16(o[nb2], ph[ks2], vhf[nb2]);
            #pragma unroll
            for (int nb2 = 0; nb2 < 8; nb2++) MMA_BF16(o[nb2], ph[ks2], vlf[nb2]);
            #pragma unroll
            for (int nb2 = 0; nb2 < 8; nb2++) MMA_BF16(o[nb2], pl[ks2], vhf[nb2]);
        }
        __syncthreads();   // stage about to be re-filled
    }

    // ---- epilogue ----
    const int b = bh >> 4, h = bh & 15;
    const float inv0 = 1.0f / l0v;
    const float inv1 = 1.0f / l1v;
    const int t0 = qt * 64 + wm * 16 + qr;
    #pragma unroll
    for (int nb2 = 0; nb2 < 8; nb2++) {
        const int d = nb2 * 8 + qc * 2;
        {
            const size_t idx = (size_t)(b * Ts + t0) * Cc + h * Dd + d;
            __nv_bfloat16 h0, lo0, h1, lo1;
            split2(o[nb2][0] * inv0, h0, lo0);
            split2(o[nb2][1] * inv0, h1, lo1);
            *(uint32_t*)&g_yhi[idx] = pack2(h0, h1);
            *(uint32_t*)&g_ylo[idx] = pack2(lo0, lo1);
        }
        {
            const size_t idx = (size_t)(b * Ts + t0 + 8) * Cc + h * Dd + d;
            __nv_bfloat16 h0, lo0, h1, lo1;
            split2(o[nb2][2] * inv1, h0, lo0);
            split2(o[nb2][3] * inv1, h1, lo1);
            *(uint32_t*)&g_yhi[idx] = pack2(h0, h1);
            *(uint32_t*)&g_ylo[idx] = pack2(lo0, lo1);
        }
    }
}

// ---------------------------------------------------------------------------
extern "C" void kernel_launch(void* const* d_in, const int* in_sizes, int n_in,
                              void* d_out, int out_size)
{
    (void)in_sizes; (void)n_in; (void)out_size;
    const float* x     = (const float*)d_in[0];
    const float* w_qkv = (const float*)d_in[1];
    const float* b_qkv = (const float*)d_in[2];
    const float* w_out = (const float*)d_in[3];
    const float* b_out = (const float*)d_in[4];
    float* out = (float*)d_out;

    cudaFuncSetAttribute(gemm_mma<0, Nqkv>,
                         cudaFuncAttributeMaxDynamicSharedMemorySize, GEMM_SMEM);
    cudaFuncSetAttribute(gemm_mma<1, Cc>,
                         cudaFuncAttributeMaxDynamicSharedMemorySize, GEMM_SMEM);
    cudaFuncSetAttribute(attn_kernel,
                         cudaFuncAttributeMaxDynamicSharedMemorySize, ATTN_SMEM);

    // 0) Pre-split x and weights
    split_x_kernel<<<(Mtot*Kdim)/(256*4), 256>>>(x);
    transpose_split_kernel<0, Nqkv><<<dim3(Nqkv/32, Kdim/32), dim3(32,8)>>>(w_qkv);
    transpose_split_kernel<1, Cc><<<dim3(Cc/32, Kdim/32), dim3(32,8)>>>(w_out);

    // 1) QKV projection
    gemm_mma<0, Nqkv><<<dim3(Nqkv/BN, Mtot/BM), 256, GEMM_SMEM>>>(b_qkv, nullptr);

    // 2) MMA flash attention (cp.async prefetch)
    attn_kernel<<<dim3(Ts/64, Bb*Hh), 128, ATTN_SMEM>>>();

    // 3) Output projection
    gemm_mma<1, Cc><<<dim3(Cc/BN, Mtot/BM), 256, GEMM_SMEM>>>(b_out, out);
}